// round 1
// baseline (speedup 1.0000x reference)
#include <cuda_runtime.h>
#include <cuda_bf16.h>
#include <cstdint>
#include <cstddef>

// ---------------- problem constants ----------------
#define BATCH 4
#define SEQ   2048
#define DMODEL 1024
#define NHEADS 16
#define HDIM   64
#define DFF    4096
#define MROWS  (BATCH*SEQ)          // 8192
#define LN_EPS 1e-5f

// ---------------- scratch (device globals; no allocations allowed) ----------
__device__ float g_h  [(size_t)MROWS * DMODEL];     // LN output          32 MB
__device__ float g_qkv[(size_t)MROWS * 3 * DMODEL]; // qkv                96 MB
__device__ float g_o  [(size_t)MROWS * DMODEL];     // attention output   32 MB
__device__ float g_h2 [(size_t)MROWS * DFF];        // gelu(fc1)         128 MB

// ---------------- helpers ----------------
__device__ __forceinline__ float gelu_exact(float x) {
    return 0.5f * x * (1.0f + erff(x * 0.70710678118654752f));
}

// ---------------- LayerNorm: one block per row, 256 threads, D=1024 --------
__global__ __launch_bounds__(256) void layernorm_kernel(
    const float* __restrict__ x, const float* __restrict__ g,
    const float* __restrict__ b, float* __restrict__ out)
{
    int row = blockIdx.x;
    const float4* xr = (const float4*)(x + (size_t)row * DMODEL);
    float4 v = xr[threadIdx.x];                       // 256*4 = 1024
    float s  = v.x + v.y + v.z + v.w;
    float sq = v.x*v.x + v.y*v.y + v.z*v.z + v.w*v.w;
    #pragma unroll
    for (int o = 16; o; o >>= 1) {
        s  += __shfl_xor_sync(0xffffffffu, s,  o);
        sq += __shfl_xor_sync(0xffffffffu, sq, o);
    }
    __shared__ float ss[8], ssq[8];
    int w = threadIdx.x >> 5, lane = threadIdx.x & 31;
    if (lane == 0) { ss[w] = s; ssq[w] = sq; }
    __syncthreads();
    float st = 0.f, sqt = 0.f;
    #pragma unroll
    for (int k = 0; k < 8; k++) { st += ss[k]; sqt += ssq[k]; }
    float mean = st * (1.0f / DMODEL);
    float var  = sqt * (1.0f / DMODEL) - mean * mean;
    float inv  = rsqrtf(var + LN_EPS);
    const float4* g4 = (const float4*)g;
    const float4* b4 = (const float4*)b;
    float4 gg = g4[threadIdx.x], bb = b4[threadIdx.x];
    float4 o4;
    o4.x = (v.x - mean) * inv * gg.x + bb.x;
    o4.y = (v.y - mean) * inv * gg.y + bb.y;
    o4.z = (v.z - mean) * inv * gg.z + bb.z;
    o4.w = (v.w - mean) * inv * gg.w + bb.w;
    ((float4*)(out + (size_t)row * DMODEL))[threadIdx.x] = o4;
}

// ---------------- SGEMM: C[M,N] = A[M,K] @ B[N,K]^T + bias (+gelu/+resid) --
// MODE 0: bias;  MODE 1: gelu(bias);  MODE 2: bias + residual R[M,N]
// BM=BN=128, BK=8, 256 threads, 8x8 per thread. M,N,K multiples of 128.
template<int MODE>
__global__ __launch_bounds__(256) void sgemm_kernel(
    const float* __restrict__ A, const float* __restrict__ B,
    const float* __restrict__ bias, const float* __restrict__ R,
    float* __restrict__ C, int M, int N, int K)
{
    __shared__ float As[8][128];
    __shared__ float Bs[8][128];

    const int bm = blockIdx.y * 128;
    const int bn = blockIdx.x * 128;
    const int tid = threadIdx.x;

    const int a_r = tid >> 1;            // 0..127
    const int a_c = (tid & 1) * 4;       // 0 or 4
    const int tx = tid & 15;             // 0..15
    const int ty = tid >> 4;             // 0..15

    const float* Aptr = A + (size_t)(bm + a_r) * K + a_c;
    const float* Bptr = B + (size_t)(bn + a_r) * K + a_c;

    float acc[8][8];
    #pragma unroll
    for (int i = 0; i < 8; i++)
        #pragma unroll
        for (int j = 0; j < 8; j++) acc[i][j] = 0.f;

    for (int k0 = 0; k0 < K; k0 += 8) {
        float4 av = *(const float4*)(Aptr + k0);
        float4 bv = *(const float4*)(Bptr + k0);
        As[a_c + 0][a_r] = av.x; As[a_c + 1][a_r] = av.y;
        As[a_c + 2][a_r] = av.z; As[a_c + 3][a_r] = av.w;
        Bs[a_c + 0][a_r] = bv.x; Bs[a_c + 1][a_r] = bv.y;
        Bs[a_c + 2][a_r] = bv.z; Bs[a_c + 3][a_r] = bv.w;
        __syncthreads();
        #pragma unroll
        for (int k = 0; k < 8; k++) {
            float ar[8], br[8];
            *(float4*)&ar[0] = *(const float4*)&As[k][ty * 8];
            *(float4*)&ar[4] = *(const float4*)&As[k][ty * 8 + 4];
            *(float4*)&br[0] = *(const float4*)&Bs[k][tx * 8];
            *(float4*)&br[4] = *(const float4*)&Bs[k][tx * 8 + 4];
            #pragma unroll
            for (int i = 0; i < 8; i++)
                #pragma unroll
                for (int j = 0; j < 8; j++)
                    acc[i][j] += ar[i] * br[j];
        }
        __syncthreads();
    }

    // epilogue
    const int colbase = bn + tx * 8;
    float bvals[8];
    *(float4*)&bvals[0] = *(const float4*)&bias[colbase];
    *(float4*)&bvals[4] = *(const float4*)&bias[colbase + 4];
    #pragma unroll
    for (int i = 0; i < 8; i++) {
        int row = bm + ty * 8 + i;
        float* Crow = C + (size_t)row * N + colbase;
        float vals[8];
        #pragma unroll
        for (int j = 0; j < 8; j++) {
            float v = acc[i][j] + bvals[j];
            if (MODE == 1) v = gelu_exact(v);
            vals[j] = v;
        }
        if (MODE == 2) {
            const float* Rrow = R + (size_t)row * N + colbase;
            float rv[8];
            *(float4*)&rv[0] = *(const float4*)&Rrow[0];
            *(float4*)&rv[4] = *(const float4*)&Rrow[4];
            #pragma unroll
            for (int j = 0; j < 8; j++) vals[j] += rv[j];
        }
        *(float4*)&Crow[0] = *(const float4*)&vals[0];
        *(float4*)&Crow[4] = *(const float4*)&vals[4];
    }
}

// ---------------- causal flash attention --------------------------------
// grid: (SEQ/128, BATCH*NHEADS), block: 128 threads, 1 query/thread.
// qkv layout: [B, S, 3, H, hd] contiguous (row stride 3*DMODEL).
__global__ __launch_bounds__(128) void attn_kernel(
    const float* __restrict__ qkv, float* __restrict__ o)
{
    const int ROWSTRIDE = 3 * DMODEL;   // 3072
    const int bh = blockIdx.y;
    const int b = bh / NHEADS;
    const int h = bh % NHEADS;
    const int i = blockIdx.x * 128 + threadIdx.x;   // query index in [0,SEQ)
    const int tid = threadIdx.x;

    const float* qbase = qkv + (size_t)b * SEQ * ROWSTRIDE + 0 * DMODEL + h * HDIM;
    const float* kbase = qkv + (size_t)b * SEQ * ROWSTRIDE + 1 * DMODEL + h * HDIM;
    const float* vbase = qkv + (size_t)b * SEQ * ROWSTRIDE + 2 * DMODEL + h * HDIM;

    float q[HDIM];
    const float scale = 0.125f;  // 1/sqrt(64)
    #pragma unroll
    for (int d = 0; d < HDIM; d += 4) {
        float4 t = *(const float4*)(qbase + (size_t)i * ROWSTRIDE + d);
        q[d+0] = t.x * scale; q[d+1] = t.y * scale;
        q[d+2] = t.z * scale; q[d+3] = t.w * scale;
    }

    float o_acc[HDIM];
    #pragma unroll
    for (int d = 0; d < HDIM; d++) o_acc[d] = 0.f;
    float m = -1e30f, l = 0.f;

    __shared__ float Ks[64][64];
    __shared__ float Vs[64][64];

    const int ntiles = blockIdx.x * 2 + 2;   // 64-key tiles covering [0, qmax]
    for (int t = 0; t < ntiles; t++) {
        const int j0 = t * 64;
        __syncthreads();
        // cooperative load: 64x64 floats = 1024 float4 per matrix, 8 per thread
        #pragma unroll
        for (int u = 0; u < 8; u++) {
            int idx = u * 128 + tid;
            int r = idx >> 4;
            int c = (idx & 15) << 2;
            *(float4*)&Ks[r][c] = *(const float4*)(kbase + (size_t)(j0 + r) * ROWSTRIDE + c);
            *(float4*)&Vs[r][c] = *(const float4*)(vbase + (size_t)(j0 + r) * ROWSTRIDE + c);
        }
        __syncthreads();

        #pragma unroll
        for (int c0 = 0; c0 < 64; c0 += 16) {
            float s[16];
            float mc = -1e30f;
            #pragma unroll
            for (int j = 0; j < 16; j++) {
                int jj = j0 + c0 + j;
                float acc = 0.f;
                #pragma unroll
                for (int d4 = 0; d4 < 16; d4++) {
                    float4 kk = *(const float4*)&Ks[c0 + j][d4 * 4];
                    acc += q[d4*4+0]*kk.x + q[d4*4+1]*kk.y
                         + q[d4*4+2]*kk.z + q[d4*4+3]*kk.w;
                }
                s[j] = (jj <= i) ? acc : -1e30f;
                mc = fmaxf(mc, s[j]);
            }
            float mnew = fmaxf(m, mc);
            float corr = __expf(m - mnew);
            float psum = 0.f;
            #pragma unroll
            for (int j = 0; j < 16; j++) {
                s[j] = __expf(s[j] - mnew);
                psum += s[j];
            }
            l = l * corr + psum;
            m = mnew;
            #pragma unroll
            for (int d = 0; d < HDIM; d++) o_acc[d] *= corr;
            #pragma unroll
            for (int j = 0; j < 16; j++) {
                float pj = s[j];
                #pragma unroll
                for (int d4 = 0; d4 < 16; d4++) {
                    float4 vv = *(const float4*)&Vs[c0 + j][d4 * 4];
                    o_acc[d4*4+0] += pj * vv.x;
                    o_acc[d4*4+1] += pj * vv.y;
                    o_acc[d4*4+2] += pj * vv.z;
                    o_acc[d4*4+3] += pj * vv.w;
                }
            }
        }
    }

    float inv = 1.f / l;
    float* orow = o + (size_t)(b * SEQ + i) * DMODEL + h * HDIM;
    #pragma unroll
    for (int d = 0; d < HDIM; d += 4) {
        float4 t;
        t.x = o_acc[d+0]*inv; t.y = o_acc[d+1]*inv;
        t.z = o_acc[d+2]*inv; t.w = o_acc[d+3]*inv;
        *(float4*)(orow + d) = t;
    }
}

// ---------------- launch ----------------
extern "C" void kernel_launch(void* const* d_in, const int* in_sizes, int n_in,
                              void* d_out, int out_size)
{
    const float* x     = (const float*)d_in[0];
    const float* ln1_g = (const float*)d_in[1];
    const float* ln1_b = (const float*)d_in[2];
    const float* qkv_w = (const float*)d_in[3];
    const float* qkv_b = (const float*)d_in[4];
    const float* out_w = (const float*)d_in[5];
    const float* out_b = (const float*)d_in[6];
    const float* ln2_g = (const float*)d_in[7];
    const float* ln2_b = (const float*)d_in[8];
    const float* fc1_w = (const float*)d_in[9];
    const float* fc1_b = (const float*)d_in[10];
    const float* fc2_w = (const float*)d_in[11];
    const float* fc2_b = (const float*)d_in[12];
    // d_in[13] = mask: causal, handled analytically
    float* out = (float*)d_out;

    static float *p_h = nullptr, *p_qkv = nullptr, *p_o = nullptr, *p_h2 = nullptr;
    if (!p_h) {
        cudaGetSymbolAddress((void**)&p_h,   g_h);
        cudaGetSymbolAddress((void**)&p_qkv, g_qkv);
        cudaGetSymbolAddress((void**)&p_o,   g_o);
        cudaGetSymbolAddress((void**)&p_h2,  g_h2);
    }

    // 1. h = LN1(x)
    layernorm_kernel<<<MROWS, 256>>>(x, ln1_g, ln1_b, p_h);
    // 2. qkv = h @ qkv_w^T + qkv_b        [8192, 3072]
    sgemm_kernel<0><<<dim3(3 * DMODEL / 128, MROWS / 128), 256>>>(
        p_h, qkv_w, qkv_b, nullptr, p_qkv, MROWS, 3 * DMODEL, DMODEL);
    // 3. o = causal attention(qkv)        [8192, 1024]
    attn_kernel<<<dim3(SEQ / 128, BATCH * NHEADS), 128>>>(p_qkv, p_o);
    // 4. x1 = x + o @ out_w^T + out_b  -> d_out
    sgemm_kernel<2><<<dim3(DMODEL / 128, MROWS / 128), 256>>>(
        p_o, out_w, out_b, x, out, MROWS, DMODEL, DMODEL);
    // 5. h = LN2(x1)
    layernorm_kernel<<<MROWS, 256>>>(out, ln2_g, ln2_b, p_h);
    // 6. h2 = gelu(h @ fc1_w^T + fc1_b)   [8192, 4096]
    sgemm_kernel<1><<<dim3(DFF / 128, MROWS / 128), 256>>>(
        p_h, fc1_w, fc1_b, nullptr, p_h2, MROWS, DFF, DMODEL);
    // 7. out = x1 + h2 @ fc2_w^T + fc2_b  (in-place residual)
    sgemm_kernel<2><<<dim3(DMODEL / 128, MROWS / 128), 256>>>(
        p_h2, fc2_w, fc2_b, out, out, MROWS, DMODEL, DFF);
}

// round 2
// speedup vs baseline: 1.7151x; 1.7151x over previous
#include <cuda_runtime.h>
#include <cuda_bf16.h>
#include <cstdint>
#include <cstddef>

// ---------------- problem constants ----------------
#define BATCH 4
#define SEQ   2048
#define DMODEL 1024
#define NHEADS 16
#define HDIM   64
#define DFF    4096
#define MROWS  (BATCH*SEQ)          // 8192
#define LN_EPS 1e-5f

typedef __nv_bfloat16  bf16;
typedef __nv_bfloat162 bf162;

// ---------------- scratch (device globals; no allocations allowed) ----------
__device__ float g_qkv [(size_t)MROWS * 3 * DMODEL];   // fp32 qkv for attention
__device__ bf16  g_h_hi[(size_t)MROWS * DMODEL];
__device__ bf16  g_h_lo[(size_t)MROWS * DMODEL];
__device__ bf16  g_o_hi[(size_t)MROWS * DMODEL];
__device__ bf16  g_o_lo[(size_t)MROWS * DMODEL];
__device__ bf16  g_h2_hi[(size_t)MROWS * DFF];
__device__ bf16  g_h2_lo[(size_t)MROWS * DFF];
__device__ bf16  g_wqkv_hi[(size_t)3*DMODEL*DMODEL];
__device__ bf16  g_wqkv_lo[(size_t)3*DMODEL*DMODEL];
__device__ bf16  g_wout_hi[(size_t)DMODEL*DMODEL];
__device__ bf16  g_wout_lo[(size_t)DMODEL*DMODEL];
__device__ bf16  g_wfc1_hi[(size_t)DFF*DMODEL];
__device__ bf16  g_wfc1_lo[(size_t)DFF*DMODEL];
__device__ bf16  g_wfc2_hi[(size_t)DMODEL*DFF];
__device__ bf16  g_wfc2_lo[(size_t)DMODEL*DFF];

// ---------------- helpers ----------------
__device__ __forceinline__ float gelu_exact(float x) {
    return 0.5f * x * (1.0f + erff(x * 0.70710678118654752f));
}
__device__ __forceinline__ void split2(float v, bf16& h, bf16& l) {
    h = __float2bfloat16(v);
    l = __float2bfloat16(v - __bfloat162float(h));
}
__device__ __forceinline__ void cp16(void* dst_smem, const void* src_gmem) {
    unsigned s = (unsigned)__cvta_generic_to_shared(dst_smem);
    asm volatile("cp.async.cg.shared.global [%0], [%1], 16;" :: "r"(s), "l"(src_gmem) : "memory");
}
__device__ __forceinline__ void cp_commit() {
    asm volatile("cp.async.commit_group;" ::: "memory");
}
template<int N>
__device__ __forceinline__ void cp_wait() {
    asm volatile("cp.async.wait_group %0;" :: "n"(N) : "memory");
}
__device__ __forceinline__ void mma16816(float* c, const uint32_t* a, const uint32_t* b) {
    asm volatile(
        "mma.sync.aligned.m16n8k16.row.col.f32.bf16.bf16.f32 "
        "{%0,%1,%2,%3}, {%4,%5,%6,%7}, {%8,%9}, {%0,%1,%2,%3};"
        : "+f"(c[0]), "+f"(c[1]), "+f"(c[2]), "+f"(c[3])
        : "r"(a[0]), "r"(a[1]), "r"(a[2]), "r"(a[3]), "r"(b[0]), "r"(b[1]));
}

// ---------------- weight split kernel (fp32 -> bf16 hi/lo) -----------------
__global__ __launch_bounds__(256) void split_kernel(
    const float* __restrict__ in, bf16* __restrict__ hi, bf16* __restrict__ lo)
{
    int i = blockIdx.x * blockDim.x + threadIdx.x;   // one float4 per thread
    float4 v = ((const float4*)in)[i];
    bf16 h0,h1,h2,h3,l0,l1,l2,l3;
    split2(v.x,h0,l0); split2(v.y,h1,l1); split2(v.z,h2,l2); split2(v.w,h3,l3);
    bf162 ha; ha.x=h0; ha.y=h1;  bf162 hb; hb.x=h2; hb.y=h3;
    bf162 la; la.x=l0; la.y=l1;  bf162 lb; lb.x=l2; lb.y=l3;
    ((bf162*)hi)[2*i]   = ha; ((bf162*)hi)[2*i+1] = hb;
    ((bf162*)lo)[2*i]   = la; ((bf162*)lo)[2*i+1] = lb;
}

// ---------------- LayerNorm -> split bf16 hi/lo ----------------------------
__global__ __launch_bounds__(256) void layernorm_split_kernel(
    const float* __restrict__ x, const float* __restrict__ g,
    const float* __restrict__ b, bf16* __restrict__ hi, bf16* __restrict__ lo)
{
    int row = blockIdx.x;
    const float4* xr = (const float4*)(x + (size_t)row * DMODEL);
    float4 v = xr[threadIdx.x];
    float s  = v.x + v.y + v.z + v.w;
    float sq = v.x*v.x + v.y*v.y + v.z*v.z + v.w*v.w;
    #pragma unroll
    for (int o = 16; o; o >>= 1) {
        s  += __shfl_xor_sync(0xffffffffu, s,  o);
        sq += __shfl_xor_sync(0xffffffffu, sq, o);
    }
    __shared__ float ss[8], ssq[8];
    int w = threadIdx.x >> 5, lane = threadIdx.x & 31;
    if (lane == 0) { ss[w] = s; ssq[w] = sq; }
    __syncthreads();
    float st = 0.f, sqt = 0.f;
    #pragma unroll
    for (int k = 0; k < 8; k++) { st += ss[k]; sqt += ssq[k]; }
    float mean = st * (1.0f / DMODEL);
    float var  = sqt * (1.0f / DMODEL) - mean * mean;
    float inv  = rsqrtf(var + LN_EPS);
    float4 gg = ((const float4*)g)[threadIdx.x];
    float4 bb = ((const float4*)b)[threadIdx.x];
    float o0 = (v.x - mean) * inv * gg.x + bb.x;
    float o1 = (v.y - mean) * inv * gg.y + bb.y;
    float o2 = (v.z - mean) * inv * gg.z + bb.z;
    float o3 = (v.w - mean) * inv * gg.w + bb.w;
    bf16 h0,h1,h2,h3,l0,l1,l2,l3;
    split2(o0,h0,l0); split2(o1,h1,l1); split2(o2,h2,l2); split2(o3,h3,l3);
    bf162 ha; ha.x=h0; ha.y=h1;  bf162 hb; hb.x=h2; hb.y=h3;
    bf162 la; la.x=l0; la.y=l1;  bf162 lb; lb.x=l2; lb.y=l3;
    bf162* hp = (bf162*)(hi + (size_t)row * DMODEL);
    bf162* lp = (bf162*)(lo + (size_t)row * DMODEL);
    hp[2*threadIdx.x] = ha; hp[2*threadIdx.x+1] = hb;
    lp[2*threadIdx.x] = la; lp[2*threadIdx.x+1] = lb;
}

// ---------------- bf16x3 tensor-core GEMM ----------------------------------
// C[M,N] = (Ah+Al)[M,K] @ (Bh+Bl)[N,K]^T + bias, dropping Al*Bl.
// MODE 0: fp32 out (bias); MODE 1: gelu -> split bf16 out; MODE 2: fp32 bias+resid
#define BM 128
#define BN 128
#define BK 32
#define SSTRIDE 40                      // bf16 elems per smem row (padded)
#define TILE_B  (BM * SSTRIDE * 2)      // 10240 bytes
#define STAGE_B (4 * TILE_B)            // 40960 bytes

__device__ __forceinline__ uint32_t lds32(const bf16* base, int r, int c) {
    return *reinterpret_cast<const uint32_t*>(base + r * SSTRIDE + c);
}

template<int MODE>
__global__ __launch_bounds__(256, 2) void gemm_bf16x3(
    const bf16* __restrict__ Ah, const bf16* __restrict__ Al,
    const bf16* __restrict__ Bh, const bf16* __restrict__ Bl,
    const float* __restrict__ bias, const float* __restrict__ R,
    float* __restrict__ C, bf16* __restrict__ Chi, bf16* __restrict__ Clo,
    int M, int N, int K)
{
    extern __shared__ char smem[];
    const int tid  = threadIdx.x;
    const int bm = blockIdx.y * BM, bn = blockIdx.x * BN;
    const int warp = tid >> 5, lane = tid & 31;
    const int wm = warp >> 2, wn = warp & 3;     // warps: 2 (m) x 4 (n)
    const int gg = lane >> 2, qt = lane & 3;

    const bf16* gmat0 = Ah + (size_t)bm * K;
    const bf16* gmat1 = Al + (size_t)bm * K;
    const bf16* gmat2 = Bh + (size_t)bn * K;
    const bf16* gmat3 = Bl + (size_t)bn * K;

    float acc[4][4][4];
    #pragma unroll
    for (int i = 0; i < 4; i++)
        #pragma unroll
        for (int j = 0; j < 4; j++)
            #pragma unroll
            for (int q = 0; q < 4; q++) acc[i][j][q] = 0.f;

    const int NK = K / BK;

    // cp.async issue of one stage
    auto issue = [&](int k0, int st) {
        char* sb = smem + st * STAGE_B;
        #pragma unroll
        for (int c = 0; c < 2; c++) {
            int chunk = tid + c * 256;            // 512 chunks per matrix
            int row = chunk >> 2, col = chunk & 3;
            size_t goff = (size_t)row * K + k0 + col * 8;
            char*  sdst = sb + row * (SSTRIDE * 2) + col * 16;
            cp16(sdst + 0 * TILE_B, gmat0 + goff);
            cp16(sdst + 1 * TILE_B, gmat1 + goff);
            cp16(sdst + 2 * TILE_B, gmat2 + goff);
            cp16(sdst + 3 * TILE_B, gmat3 + goff);
        }
    };

    issue(0, 0); cp_commit();

    for (int ks = 0; ks < NK; ks++) {
        const int cur = ks & 1;
        if (ks + 1 < NK) { issue((ks + 1) * BK, cur ^ 1); cp_commit(); cp_wait<1>(); }
        else             { cp_wait<0>(); }
        __syncthreads();

        const bf16* sAh = (const bf16*)(smem + cur * STAGE_B);
        const bf16* sAl = sAh + BM * SSTRIDE;
        const bf16* sBh = sAl + BM * SSTRIDE;
        const bf16* sBl = sBh + BM * SSTRIDE;

        #pragma unroll
        for (int kk = 0; kk < BK; kk += 16) {
            uint32_t afr[4][4], bfr[4][2];
            // hi A fragments
            #pragma unroll
            for (int mt = 0; mt < 4; mt++) {
                int r = wm * 64 + mt * 16 + gg;
                afr[mt][0] = lds32(sAh, r,     kk + 2*qt);
                afr[mt][1] = lds32(sAh, r + 8, kk + 2*qt);
                afr[mt][2] = lds32(sAh, r,     kk + 2*qt + 8);
                afr[mt][3] = lds32(sAh, r + 8, kk + 2*qt + 8);
            }
            // hi B fragments
            #pragma unroll
            for (int nt = 0; nt < 4; nt++) {
                int n = wn * 32 + nt * 8 + gg;
                bfr[nt][0] = lds32(sBh, n, kk + 2*qt);
                bfr[nt][1] = lds32(sBh, n, kk + 2*qt + 8);
            }
            // Ah * Bh
            #pragma unroll
            for (int mt = 0; mt < 4; mt++)
                #pragma unroll
                for (int nt = 0; nt < 4; nt++)
                    mma16816(acc[mt][nt], afr[mt], bfr[nt]);
            // Al * Bh
            {
                uint32_t afl[4][4];
                #pragma unroll
                for (int mt = 0; mt < 4; mt++) {
                    int r = wm * 64 + mt * 16 + gg;
                    afl[mt][0] = lds32(sAl, r,     kk + 2*qt);
                    afl[mt][1] = lds32(sAl, r + 8, kk + 2*qt);
                    afl[mt][2] = lds32(sAl, r,     kk + 2*qt + 8);
                    afl[mt][3] = lds32(sAl, r + 8, kk + 2*qt + 8);
                }
                #pragma unroll
                for (int mt = 0; mt < 4; mt++)
                    #pragma unroll
                    for (int nt = 0; nt < 4; nt++)
                        mma16816(acc[mt][nt], afl[mt], bfr[nt]);
            }
            // Ah * Bl (reuse bfr regs)
            #pragma unroll
            for (int nt = 0; nt < 4; nt++) {
                int n = wn * 32 + nt * 8 + gg;
                bfr[nt][0] = lds32(sBl, n, kk + 2*qt);
                bfr[nt][1] = lds32(sBl, n, kk + 2*qt + 8);
            }
            #pragma unroll
            for (int mt = 0; mt < 4; mt++)
                #pragma unroll
                for (int nt = 0; nt < 4; nt++)
                    mma16816(acc[mt][nt], afr[mt], bfr[nt]);
        }
        __syncthreads();
    }

    // ---------------- epilogue ----------------
    #pragma unroll
    for (int mt = 0; mt < 4; mt++) {
        #pragma unroll
        for (int nt = 0; nt < 4; nt++) {
            int r  = bm + wm * 64 + mt * 16 + gg;
            int c0 = bn + wn * 32 + nt * 8 + 2 * qt;
            float2 bv = *(const float2*)(bias + c0);
            float v00 = acc[mt][nt][0] + bv.x;
            float v01 = acc[mt][nt][1] + bv.y;
            float v10 = acc[mt][nt][2] + bv.x;
            float v11 = acc[mt][nt][3] + bv.y;
            if (MODE == 2) {
                float2 r0 = *(const float2*)(R + (size_t)r * N + c0);
                float2 r1 = *(const float2*)(R + (size_t)(r + 8) * N + c0);
                v00 += r0.x; v01 += r0.y; v10 += r1.x; v11 += r1.y;
            }
            if (MODE == 1) {
                v00 = gelu_exact(v00); v01 = gelu_exact(v01);
                v10 = gelu_exact(v10); v11 = gelu_exact(v11);
                bf16 h0,h1,h2,h3,l0,l1,l2,l3;
                split2(v00,h0,l0); split2(v01,h1,l1);
                split2(v10,h2,l2); split2(v11,h3,l3);
                bf162 pa; pa.x=h0; pa.y=h1;  bf162 pb; pb.x=h2; pb.y=h3;
                bf162 qa; qa.x=l0; qa.y=l1;  bf162 qb; qb.x=l2; qb.y=l3;
                *(bf162*)(Chi + (size_t)r * N + c0)       = pa;
                *(bf162*)(Chi + (size_t)(r + 8) * N + c0) = pb;
                *(bf162*)(Clo + (size_t)r * N + c0)       = qa;
                *(bf162*)(Clo + (size_t)(r + 8) * N + c0) = qb;
            } else {
                float2 o0 = make_float2(v00, v01);
                float2 o1 = make_float2(v10, v11);
                *(float2*)(C + (size_t)r * N + c0)       = o0;
                *(float2*)(C + (size_t)(r + 8) * N + c0) = o1;
            }
        }
    }
}

// ---------------- causal flash attention (fp32, split-bf16 output) ---------
__global__ __launch_bounds__(128) void attn_kernel(
    const float* __restrict__ qkv, bf16* __restrict__ o_hi, bf16* __restrict__ o_lo)
{
    const int ROWSTRIDE = 3 * DMODEL;   // 3072
    const int bh = blockIdx.y;
    const int b = bh / NHEADS;
    const int h = bh % NHEADS;
    const int i = blockIdx.x * 128 + threadIdx.x;
    const int tid = threadIdx.x;

    const float* qbase = qkv + (size_t)b * SEQ * ROWSTRIDE + 0 * DMODEL + h * HDIM;
    const float* kbase = qkv + (size_t)b * SEQ * ROWSTRIDE + 1 * DMODEL + h * HDIM;
    const float* vbase = qkv + (size_t)b * SEQ * ROWSTRIDE + 2 * DMODEL + h * HDIM;

    float q[HDIM];
    const float scale = 0.125f;
    #pragma unroll
    for (int d = 0; d < HDIM; d += 4) {
        float4 t = *(const float4*)(qbase + (size_t)i * ROWSTRIDE + d);
        q[d+0] = t.x * scale; q[d+1] = t.y * scale;
        q[d+2] = t.z * scale; q[d+3] = t.w * scale;
    }

    float o_acc[HDIM];
    #pragma unroll
    for (int d = 0; d < HDIM; d++) o_acc[d] = 0.f;
    float m = -1e30f, l = 0.f;

    __shared__ float Ks[64][64];
    __shared__ float Vs[64][64];

    const int ntiles = blockIdx.x * 2 + 2;
    for (int t = 0; t < ntiles; t++) {
        const int j0 = t * 64;
        __syncthreads();
        #pragma unroll
        for (int u = 0; u < 8; u++) {
            int idx = u * 128 + tid;
            int r = idx >> 4;
            int c = (idx & 15) << 2;
            *(float4*)&Ks[r][c] = *(const float4*)(kbase + (size_t)(j0 + r) * ROWSTRIDE + c);
            *(float4*)&Vs[r][c] = *(const float4*)(vbase + (size_t)(j0 + r) * ROWSTRIDE + c);
        }
        __syncthreads();

        #pragma unroll
        for (int c0 = 0; c0 < 64; c0 += 16) {
            float s[16];
            float mc = -1e30f;
            #pragma unroll
            for (int j = 0; j < 16; j++) {
                int jj = j0 + c0 + j;
                float acc = 0.f;
                #pragma unroll
                for (int d4 = 0; d4 < 16; d4++) {
                    float4 kk = *(const float4*)&Ks[c0 + j][d4 * 4];
                    acc += q[d4*4+0]*kk.x + q[d4*4+1]*kk.y
                         + q[d4*4+2]*kk.z + q[d4*4+3]*kk.w;
                }
                s[j] = (jj <= i) ? acc : -1e30f;
                mc = fmaxf(mc, s[j]);
            }
            float mnew = fmaxf(m, mc);
            float corr = __expf(m - mnew);
            float psum = 0.f;
            #pragma unroll
            for (int j = 0; j < 16; j++) {
                s[j] = __expf(s[j] - mnew);
                psum += s[j];
            }
            l = l * corr + psum;
            m = mnew;
            #pragma unroll
            for (int d = 0; d < HDIM; d++) o_acc[d] *= corr;
            #pragma unroll
            for (int j = 0; j < 16; j++) {
                float pj = s[j];
                #pragma unroll
                for (int d4 = 0; d4 < 16; d4++) {
                    float4 vv = *(const float4*)&Vs[c0 + j][d4 * 4];
                    o_acc[d4*4+0] += pj * vv.x;
                    o_acc[d4*4+1] += pj * vv.y;
                    o_acc[d4*4+2] += pj * vv.z;
                    o_acc[d4*4+3] += pj * vv.w;
                }
            }
        }
    }

    float inv = 1.f / l;
    bf16* hrow = o_hi + (size_t)(b * SEQ + i) * DMODEL + h * HDIM;
    bf16* lrow = o_lo + (size_t)(b * SEQ + i) * DMODEL + h * HDIM;
    #pragma unroll
    for (int d = 0; d < HDIM; d += 2) {
        bf16 h0,h1,l0,l1;
        split2(o_acc[d+0]*inv, h0, l0);
        split2(o_acc[d+1]*inv, h1, l1);
        bf162 hp; hp.x=h0; hp.y=h1;
        bf162 lp; lp.x=l0; lp.y=l1;
        *(bf162*)(hrow + d) = hp;
        *(bf162*)(lrow + d) = lp;
    }
}

// ---------------- launch ----------------
extern "C" void kernel_launch(void* const* d_in, const int* in_sizes, int n_in,
                              void* d_out, int out_size)
{
    const float* x     = (const float*)d_in[0];
    const float* ln1_g = (const float*)d_in[1];
    const float* ln1_b = (const float*)d_in[2];
    const float* qkv_w = (const float*)d_in[3];
    const float* qkv_b = (const float*)d_in[4];
    const float* out_w = (const float*)d_in[5];
    const float* out_b = (const float*)d_in[6];
    const float* ln2_g = (const float*)d_in[7];
    const float* ln2_b = (const float*)d_in[8];
    const float* fc1_w = (const float*)d_in[9];
    const float* fc1_b = (const float*)d_in[10];
    const float* fc2_w = (const float*)d_in[11];
    const float* fc2_b = (const float*)d_in[12];
    float* out = (float*)d_out;

    static float *p_qkv = nullptr;
    static bf16 *p_h_hi, *p_h_lo, *p_o_hi, *p_o_lo, *p_h2_hi, *p_h2_lo;
    static bf16 *p_wqkv_hi, *p_wqkv_lo, *p_wout_hi, *p_wout_lo;
    static bf16 *p_wfc1_hi, *p_wfc1_lo, *p_wfc2_hi, *p_wfc2_lo;
    if (!p_qkv) {
        cudaGetSymbolAddress((void**)&p_qkv,    g_qkv);
        cudaGetSymbolAddress((void**)&p_h_hi,   g_h_hi);
        cudaGetSymbolAddress((void**)&p_h_lo,   g_h_lo);
        cudaGetSymbolAddress((void**)&p_o_hi,   g_o_hi);
        cudaGetSymbolAddress((void**)&p_o_lo,   g_o_lo);
        cudaGetSymbolAddress((void**)&p_h2_hi,  g_h2_hi);
        cudaGetSymbolAddress((void**)&p_h2_lo,  g_h2_lo);
        cudaGetSymbolAddress((void**)&p_wqkv_hi, g_wqkv_hi);
        cudaGetSymbolAddress((void**)&p_wqkv_lo, g_wqkv_lo);
        cudaGetSymbolAddress((void**)&p_wout_hi, g_wout_hi);
        cudaGetSymbolAddress((void**)&p_wout_lo, g_wout_lo);
        cudaGetSymbolAddress((void**)&p_wfc1_hi, g_wfc1_hi);
        cudaGetSymbolAddress((void**)&p_wfc1_lo, g_wfc1_lo);
        cudaGetSymbolAddress((void**)&p_wfc2_hi, g_wfc2_hi);
        cudaGetSymbolAddress((void**)&p_wfc2_lo, g_wfc2_lo);
    }

    const int SMEM_GEMM = 2 * STAGE_B;   // 81920 bytes
    cudaFuncSetAttribute(gemm_bf16x3<0>, cudaFuncAttributeMaxDynamicSharedMemorySize, SMEM_GEMM);
    cudaFuncSetAttribute(gemm_bf16x3<1>, cudaFuncAttributeMaxDynamicSharedMemorySize, SMEM_GEMM);
    cudaFuncSetAttribute(gemm_bf16x3<2>, cudaFuncAttributeMaxDynamicSharedMemorySize, SMEM_GEMM);

    // weight splits (cheap; run every launch for determinism)
    split_kernel<<<(3*DMODEL*DMODEL)/4/256, 256>>>(qkv_w, p_wqkv_hi, p_wqkv_lo);
    split_kernel<<<(DMODEL*DMODEL)/4/256,   256>>>(out_w, p_wout_hi, p_wout_lo);
    split_kernel<<<(DFF*DMODEL)/4/256,      256>>>(fc1_w, p_wfc1_hi, p_wfc1_lo);
    split_kernel<<<(DMODEL*DFF)/4/256,      256>>>(fc2_w, p_wfc2_hi, p_wfc2_lo);

    // 1. h = LN1(x) -> split
    layernorm_split_kernel<<<MROWS, 256>>>(x, ln1_g, ln1_b, p_h_hi, p_h_lo);
    // 2. qkv = h @ qkv_w^T + qkv_b (fp32 out)
    gemm_bf16x3<0><<<dim3(3*DMODEL/BN, MROWS/BM), 256, SMEM_GEMM>>>(
        p_h_hi, p_h_lo, p_wqkv_hi, p_wqkv_lo, qkv_b, nullptr,
        p_qkv, nullptr, nullptr, MROWS, 3*DMODEL, DMODEL);
    // 3. attention -> o split
    attn_kernel<<<dim3(SEQ/128, BATCH*NHEADS), 128>>>(p_qkv, p_o_hi, p_o_lo);
    // 4. out = x + o @ out_w^T + out_b
    gemm_bf16x3<2><<<dim3(DMODEL/BN, MROWS/BM), 256, SMEM_GEMM>>>(
        p_o_hi, p_o_lo, p_wout_hi, p_wout_lo, out_b, x,
        out, nullptr, nullptr, MROWS, DMODEL, DMODEL);
    // 5. h = LN2(out) -> split
    layernorm_split_kernel<<<MROWS, 256>>>(out, ln2_g, ln2_b, p_h_hi, p_h_lo);
    // 6. h2 = gelu(h @ fc1_w^T + fc1_b) -> split
    gemm_bf16x3<1><<<dim3(DFF/BN, MROWS/BM), 256, SMEM_GEMM>>>(
        p_h_hi, p_h_lo, p_wfc1_hi, p_wfc1_lo, fc1_b, nullptr,
        nullptr, p_h2_hi, p_h2_lo, MROWS, DFF, DMODEL);
    // 7. out = out + h2 @ fc2_w^T + fc2_b
    gemm_bf16x3<2><<<dim3(DMODEL/BN, MROWS/BM), 256, SMEM_GEMM>>>(
        p_h2_hi, p_h2_lo, p_wfc2_hi, p_wfc2_lo, fc2_b, out,
        out, nullptr, nullptr, MROWS, DMODEL, DFF);
}

// round 3
// speedup vs baseline: 4.1100x; 2.3964x over previous
#include <cuda_runtime.h>
#include <cuda_bf16.h>
#include <cstdint>
#include <cstddef>

// ---------------- problem constants ----------------
#define BATCH 4
#define SEQ   2048
#define DMODEL 1024
#define NHEADS 16
#define HDIM   64
#define DFF    4096
#define MROWS  (BATCH*SEQ)          // 8192
#define LN_EPS 1e-5f

typedef __nv_bfloat16  bf16;
typedef __nv_bfloat162 bf162;

// ---------------- scratch (device globals; no allocations allowed) ----------
__device__ bf16  g_qkvb[(size_t)MROWS * 3 * DMODEL];   // bf16 qkv for attention
__device__ bf16  g_h_hi[(size_t)MROWS * DMODEL];
__device__ bf16  g_h_lo[(size_t)MROWS * DMODEL];
__device__ bf16  g_o_hi[(size_t)MROWS * DMODEL];
__device__ bf16  g_o_lo[(size_t)MROWS * DMODEL];
__device__ bf16  g_h2_hi[(size_t)MROWS * DFF];
__device__ bf16  g_h2_lo[(size_t)MROWS * DFF];
__device__ bf16  g_wqkv_hi[(size_t)3*DMODEL*DMODEL];
__device__ bf16  g_wqkv_lo[(size_t)3*DMODEL*DMODEL];
__device__ bf16  g_wout_hi[(size_t)DMODEL*DMODEL];
__device__ bf16  g_wout_lo[(size_t)DMODEL*DMODEL];
__device__ bf16  g_wfc1_hi[(size_t)DFF*DMODEL];
__device__ bf16  g_wfc1_lo[(size_t)DFF*DMODEL];
__device__ bf16  g_wfc2_hi[(size_t)DMODEL*DFF];
__device__ bf16  g_wfc2_lo[(size_t)DMODEL*DFF];

// ---------------- helpers ----------------
__device__ __forceinline__ float gelu_exact(float x) {
    return 0.5f * x * (1.0f + erff(x * 0.70710678118654752f));
}
__device__ __forceinline__ void split2(float v, bf16& h, bf16& l) {
    h = __float2bfloat16(v);
    l = __float2bfloat16(v - __bfloat162float(h));
}
__device__ __forceinline__ uint32_t pk2(float a, float b) {
    bf162 t = __floats2bfloat162_rn(a, b);
    return *(uint32_t*)&t;
}
__device__ __forceinline__ void cp16(void* dst_smem, const void* src_gmem) {
    unsigned s = (unsigned)__cvta_generic_to_shared(dst_smem);
    asm volatile("cp.async.cg.shared.global [%0], [%1], 16;" :: "r"(s), "l"(src_gmem) : "memory");
}
__device__ __forceinline__ void cp_commit() {
    asm volatile("cp.async.commit_group;" ::: "memory");
}
template<int N>
__device__ __forceinline__ void cp_wait() {
    asm volatile("cp.async.wait_group %0;" :: "n"(N) : "memory");
}
__device__ __forceinline__ void mma16816(float* c, const uint32_t* a, const uint32_t* b) {
    asm volatile(
        "mma.sync.aligned.m16n8k16.row.col.f32.bf16.bf16.f32 "
        "{%0,%1,%2,%3}, {%4,%5,%6,%7}, {%8,%9}, {%0,%1,%2,%3};"
        : "+f"(c[0]), "+f"(c[1]), "+f"(c[2]), "+f"(c[3])
        : "r"(a[0]), "r"(a[1]), "r"(a[2]), "r"(a[3]), "r"(b[0]), "r"(b[1]));
}
__device__ __forceinline__ void ldsm_x4(uint32_t& r0, uint32_t& r1, uint32_t& r2, uint32_t& r3,
                                        const void* p) {
    uint32_t a = (uint32_t)__cvta_generic_to_shared(p);
    asm volatile("ldmatrix.sync.aligned.m8n8.x4.shared.b16 {%0,%1,%2,%3}, [%4];"
                 : "=r"(r0), "=r"(r1), "=r"(r2), "=r"(r3) : "r"(a));
}
__device__ __forceinline__ void ldsm_x4_t(uint32_t& r0, uint32_t& r1, uint32_t& r2, uint32_t& r3,
                                          const void* p) {
    uint32_t a = (uint32_t)__cvta_generic_to_shared(p);
    asm volatile("ldmatrix.sync.aligned.m8n8.x4.trans.shared.b16 {%0,%1,%2,%3}, [%4];"
                 : "=r"(r0), "=r"(r1), "=r"(r2), "=r"(r3) : "r"(a));
}

// ---------------- weight split kernel (fp32 -> bf16 hi/lo) -----------------
__global__ __launch_bounds__(256) void split_kernel(
    const float* __restrict__ in, bf16* __restrict__ hi, bf16* __restrict__ lo)
{
    int i = blockIdx.x * blockDim.x + threadIdx.x;
    float4 v = ((const float4*)in)[i];
    bf16 h0,h1,h2,h3,l0,l1,l2,l3;
    split2(v.x,h0,l0); split2(v.y,h1,l1); split2(v.z,h2,l2); split2(v.w,h3,l3);
    bf162 ha; ha.x=h0; ha.y=h1;  bf162 hb; hb.x=h2; hb.y=h3;
    bf162 la; la.x=l0; la.y=l1;  bf162 lb; lb.x=l2; lb.y=l3;
    ((bf162*)hi)[2*i]   = ha; ((bf162*)hi)[2*i+1] = hb;
    ((bf162*)lo)[2*i]   = la; ((bf162*)lo)[2*i+1] = lb;
}

// ---------------- LayerNorm -> split bf16 hi/lo ----------------------------
__global__ __launch_bounds__(256) void layernorm_split_kernel(
    const float* __restrict__ x, const float* __restrict__ g,
    const float* __restrict__ b, bf16* __restrict__ hi, bf16* __restrict__ lo)
{
    int row = blockIdx.x;
    const float4* xr = (const float4*)(x + (size_t)row * DMODEL);
    float4 v = xr[threadIdx.x];
    float s  = v.x + v.y + v.z + v.w;
    float sq = v.x*v.x + v.y*v.y + v.z*v.z + v.w*v.w;
    #pragma unroll
    for (int o = 16; o; o >>= 1) {
        s  += __shfl_xor_sync(0xffffffffu, s,  o);
        sq += __shfl_xor_sync(0xffffffffu, sq, o);
    }
    __shared__ float ss[8], ssq[8];
    int w = threadIdx.x >> 5, lane = threadIdx.x & 31;
    if (lane == 0) { ss[w] = s; ssq[w] = sq; }
    __syncthreads();
    float st = 0.f, sqt = 0.f;
    #pragma unroll
    for (int k = 0; k < 8; k++) { st += ss[k]; sqt += ssq[k]; }
    float mean = st * (1.0f / DMODEL);
    float var  = sqt * (1.0f / DMODEL) - mean * mean;
    float inv  = rsqrtf(var + LN_EPS);
    float4 gg = ((const float4*)g)[threadIdx.x];
    float4 bb = ((const float4*)b)[threadIdx.x];
    float o0 = (v.x - mean) * inv * gg.x + bb.x;
    float o1 = (v.y - mean) * inv * gg.y + bb.y;
    float o2 = (v.z - mean) * inv * gg.z + bb.z;
    float o3 = (v.w - mean) * inv * gg.w + bb.w;
    bf16 h0,h1,h2,h3,l0,l1,l2,l3;
    split2(o0,h0,l0); split2(o1,h1,l1); split2(o2,h2,l2); split2(o3,h3,l3);
    bf162 ha; ha.x=h0; ha.y=h1;  bf162 hb; hb.x=h2; hb.y=h3;
    bf162 la; la.x=l0; la.y=l1;  bf162 lb; lb.x=l2; lb.y=l3;
    bf162* hp = (bf162*)(hi + (size_t)row * DMODEL);
    bf162* lp = (bf162*)(lo + (size_t)row * DMODEL);
    hp[2*threadIdx.x] = ha; hp[2*threadIdx.x+1] = hb;
    lp[2*threadIdx.x] = la; lp[2*threadIdx.x+1] = lb;
}

// ---------------- bf16x3 tensor-core GEMM ----------------------------------
// MODE 1: gelu -> split bf16; MODE 2: fp32 bias+resid; MODE 3: bf16 out
#define BM 128
#define BN 128
#define BK 32
#define SSTRIDE 40
#define TILE_B  (BM * SSTRIDE * 2)
#define STAGE_B (4 * TILE_B)

__device__ __forceinline__ uint32_t lds32(const bf16* base, int r, int c) {
    return *reinterpret_cast<const uint32_t*>(base + r * SSTRIDE + c);
}

template<int MODE>
__global__ __launch_bounds__(256, 2) void gemm_bf16x3(
    const bf16* __restrict__ Ah, const bf16* __restrict__ Al,
    const bf16* __restrict__ Bh, const bf16* __restrict__ Bl,
    const float* __restrict__ bias, const float* __restrict__ R,
    float* __restrict__ C, bf16* __restrict__ Chi, bf16* __restrict__ Clo,
    int M, int N, int K)
{
    extern __shared__ char smem[];
    const int tid  = threadIdx.x;
    const int bm = blockIdx.y * BM, bn = blockIdx.x * BN;
    const int warp = tid >> 5, lane = tid & 31;
    const int wm = warp >> 2, wn = warp & 3;
    const int gg = lane >> 2, qt = lane & 3;

    const bf16* gmat0 = Ah + (size_t)bm * K;
    const bf16* gmat1 = Al + (size_t)bm * K;
    const bf16* gmat2 = Bh + (size_t)bn * K;
    const bf16* gmat3 = Bl + (size_t)bn * K;

    float acc[4][4][4];
    #pragma unroll
    for (int i = 0; i < 4; i++)
        #pragma unroll
        for (int j = 0; j < 4; j++)
            #pragma unroll
            for (int q = 0; q < 4; q++) acc[i][j][q] = 0.f;

    const int NK = K / BK;

    auto issue = [&](int k0, int st) {
        char* sb = smem + st * STAGE_B;
        #pragma unroll
        for (int c = 0; c < 2; c++) {
            int chunk = tid + c * 256;
            int row = chunk >> 2, col = chunk & 3;
            size_t goff = (size_t)row * K + k0 + col * 8;
            char*  sdst = sb + row * (SSTRIDE * 2) + col * 16;
            cp16(sdst + 0 * TILE_B, gmat0 + goff);
            cp16(sdst + 1 * TILE_B, gmat1 + goff);
            cp16(sdst + 2 * TILE_B, gmat2 + goff);
            cp16(sdst + 3 * TILE_B, gmat3 + goff);
        }
    };

    issue(0, 0); cp_commit();

    for (int ks = 0; ks < NK; ks++) {
        const int cur = ks & 1;
        if (ks + 1 < NK) { issue((ks + 1) * BK, cur ^ 1); cp_commit(); cp_wait<1>(); }
        else             { cp_wait<0>(); }
        __syncthreads();

        const bf16* sAh = (const bf16*)(smem + cur * STAGE_B);
        const bf16* sAl = sAh + BM * SSTRIDE;
        const bf16* sBh = sAl + BM * SSTRIDE;
        const bf16* sBl = sBh + BM * SSTRIDE;

        #pragma unroll
        for (int kk = 0; kk < BK; kk += 16) {
            uint32_t afr[4][4], bfr[4][2];
            #pragma unroll
            for (int mt = 0; mt < 4; mt++) {
                int r = wm * 64 + mt * 16 + gg;
                afr[mt][0] = lds32(sAh, r,     kk + 2*qt);
                afr[mt][1] = lds32(sAh, r + 8, kk + 2*qt);
                afr[mt][2] = lds32(sAh, r,     kk + 2*qt + 8);
                afr[mt][3] = lds32(sAh, r + 8, kk + 2*qt + 8);
            }
            #pragma unroll
            for (int nt = 0; nt < 4; nt++) {
                int n = wn * 32 + nt * 8 + gg;
                bfr[nt][0] = lds32(sBh, n, kk + 2*qt);
                bfr[nt][1] = lds32(sBh, n, kk + 2*qt + 8);
            }
            #pragma unroll
            for (int mt = 0; mt < 4; mt++)
                #pragma unroll
                for (int nt = 0; nt < 4; nt++)
                    mma16816(acc[mt][nt], afr[mt], bfr[nt]);
            {
                uint32_t afl[4][4];
                #pragma unroll
                for (int mt = 0; mt < 4; mt++) {
                    int r = wm * 64 + mt * 16 + gg;
                    afl[mt][0] = lds32(sAl, r,     kk + 2*qt);
                    afl[mt][1] = lds32(sAl, r + 8, kk + 2*qt);
                    afl[mt][2] = lds32(sAl, r,     kk + 2*qt + 8);
                    afl[mt][3] = lds32(sAl, r + 8, kk + 2*qt + 8);
                }
                #pragma unroll
                for (int mt = 0; mt < 4; mt++)
                    #pragma unroll
                    for (int nt = 0; nt < 4; nt++)
                        mma16816(acc[mt][nt], afl[mt], bfr[nt]);
            }
            #pragma unroll
            for (int nt = 0; nt < 4; nt++) {
                int n = wn * 32 + nt * 8 + gg;
                bfr[nt][0] = lds32(sBl, n, kk + 2*qt);
                bfr[nt][1] = lds32(sBl, n, kk + 2*qt + 8);
            }
            #pragma unroll
            for (int mt = 0; mt < 4; mt++)
                #pragma unroll
                for (int nt = 0; nt < 4; nt++)
                    mma16816(acc[mt][nt], afr[mt], bfr[nt]);
        }
        __syncthreads();
    }

    #pragma unroll
    for (int mt = 0; mt < 4; mt++) {
        #pragma unroll
        for (int nt = 0; nt < 4; nt++) {
            int r  = bm + wm * 64 + mt * 16 + gg;
            int c0 = bn + wn * 32 + nt * 8 + 2 * qt;
            float2 bv = *(const float2*)(bias + c0);
            float v00 = acc[mt][nt][0] + bv.x;
            float v01 = acc[mt][nt][1] + bv.y;
            float v10 = acc[mt][nt][2] + bv.x;
            float v11 = acc[mt][nt][3] + bv.y;
            if (MODE == 2) {
                float2 r0 = *(const float2*)(R + (size_t)r * N + c0);
                float2 r1 = *(const float2*)(R + (size_t)(r + 8) * N + c0);
                v00 += r0.x; v01 += r0.y; v10 += r1.x; v11 += r1.y;
            }
            if (MODE == 1) {
                v00 = gelu_exact(v00); v01 = gelu_exact(v01);
                v10 = gelu_exact(v10); v11 = gelu_exact(v11);
                bf16 h0,h1,h2,h3,l0,l1,l2,l3;
                split2(v00,h0,l0); split2(v01,h1,l1);
                split2(v10,h2,l2); split2(v11,h3,l3);
                bf162 pa; pa.x=h0; pa.y=h1;  bf162 pb; pb.x=h2; pb.y=h3;
                bf162 qa; qa.x=l0; qa.y=l1;  bf162 qb; qb.x=l2; qb.y=l3;
                *(bf162*)(Chi + (size_t)r * N + c0)       = pa;
                *(bf162*)(Chi + (size_t)(r + 8) * N + c0) = pb;
                *(bf162*)(Clo + (size_t)r * N + c0)       = qa;
                *(bf162*)(Clo + (size_t)(r + 8) * N + c0) = qb;
            } else if (MODE == 3) {
                uint32_t pa = pk2(v00, v01);
                uint32_t pb = pk2(v10, v11);
                *(uint32_t*)(Chi + (size_t)r * N + c0)       = pa;
                *(uint32_t*)(Chi + (size_t)(r + 8) * N + c0) = pb;
            } else {
                *(float2*)(C + (size_t)r * N + c0)       = make_float2(v00, v01);
                *(float2*)(C + (size_t)(r + 8) * N + c0) = make_float2(v10, v11);
            }
        }
    }
}

// ---------------- tensor-core causal flash attention -----------------------
// grid (SEQ/128, B*H), 256 threads = 8 warps, warp w owns query rows w*16..+15.
#define KSTR 72   // bf16 elems per smem row (64 data + 8 pad -> 144B stride)

__global__ __launch_bounds__(256) void attn_mma_kernel(
    const bf16* __restrict__ qkvb, bf16* __restrict__ o_hi, bf16* __restrict__ o_lo)
{
    extern __shared__ char asmem[];
    bf16* Qs = (bf16*)asmem;               // [128][KSTR]
    bf16* Ks = Qs + 128 * KSTR;            // [2][64][KSTR]
    bf16* Vs = Ks + 2 * 64 * KSTR;         // [2][64][KSTR]

    const int tid = threadIdx.x;
    const int warp = tid >> 5, lane = tid & 31;
    const int gg = lane >> 2, qt = lane & 3;
    const int g8 = lane >> 3, lr = lane & 7;
    const int qt_blk = blockIdx.x, bh = blockIdx.y;
    const int b = bh >> 4, h = bh & 15;
    const int q0 = qt_blk * 128;
    const size_t ROW = 3 * DMODEL;
    const bf16* qg = qkvb + (size_t)(b * SEQ) * ROW + h * HDIM;
    const bf16* kg = qg + DMODEL;
    const bf16* vg = qg + 2 * DMODEL;

    // ---- load Q tile 128x64 into smem ----
    #pragma unroll
    for (int u = 0; u < 4; u++) {
        int idx = tid + u * 256;           // 0..1023
        int r = idx >> 3, c = (idx & 7) * 8;
        *(uint4*)&Qs[r * KSTR + c] = *(const uint4*)(qg + (size_t)(q0 + r) * ROW + c);
    }
    __syncthreads();

    // ---- Q fragments (m16k16 x 4 k-steps), scaled by 1/8 (exact in bf16) ----
    uint32_t qf[4][4];
    {
        const bf162 sc = __floats2bfloat162_rn(0.125f, 0.125f);
        #pragma unroll
        for (int kt = 0; kt < 4; kt++) {
            const bf16* p = &Qs[(warp * 16 + (g8 & 1) * 8 + lr) * KSTR + kt * 16 + (g8 >> 1) * 8];
            ldsm_x4(qf[kt][0], qf[kt][1], qf[kt][2], qf[kt][3], p);
            #pragma unroll
            for (int i = 0; i < 4; i++) {
                bf162 v = *(bf162*)&qf[kt][i];
                v = __hmul2(v, sc);
                qf[kt][i] = *(uint32_t*)&v;
            }
        }
    }

    float oacc[8][4];
    #pragma unroll
    for (int nt = 0; nt < 8; nt++)
        #pragma unroll
        for (int i = 0; i < 4; i++) oacc[nt][i] = 0.f;
    float m0 = -1e30f, m1 = -1e30f, l0 = 0.f, l1 = 0.f;

    const int ntiles = qt_blk * 2 + 2;
    const int wbase = q0 + warp * 16;
    const int wmax  = wbase + 15;

    auto issue = [&](int t, int st) {
        #pragma unroll
        for (int u = 0; u < 2; u++) {
            int idx = tid + u * 256;       // 0..511
            int r = idx >> 3, c = (idx & 7) * 8;
            size_t goff = (size_t)(t * 64 + r) * ROW + c;
            cp16(&Ks[st * 64 * KSTR + r * KSTR + c], kg + goff);
            cp16(&Vs[st * 64 * KSTR + r * KSTR + c], vg + goff);
        }
    };

    issue(0, 0); cp_commit();

    for (int t = 0; t < ntiles; t++) {
        const int cur = t & 1;
        if (t + 1 < ntiles) { issue(t + 1, cur ^ 1); cp_commit(); cp_wait<1>(); }
        else                { cp_wait<0>(); }
        __syncthreads();

        const int j0 = t * 64;
        if (j0 <= wmax) {
            const bf16* Kt = &Ks[cur * 64 * KSTR];
            const bf16* Vt = &Vs[cur * 64 * KSTR];

            // ---- S = Q K^T ----
            float sacc[8][4];
            #pragma unroll
            for (int nt = 0; nt < 8; nt++)
                #pragma unroll
                for (int i = 0; i < 4; i++) sacc[nt][i] = 0.f;

            #pragma unroll
            for (int kt = 0; kt < 4; kt++) {
                uint32_t bfr[8][2];
                #pragma unroll
                for (int np = 0; np < 4; np++) {
                    const bf16* p = &Kt[(np * 16 + (g8 >> 1) * 8 + lr) * KSTR + kt * 16 + (g8 & 1) * 8];
                    ldsm_x4(bfr[2*np][0], bfr[2*np][1], bfr[2*np+1][0], bfr[2*np+1][1], p);
                }
                #pragma unroll
                for (int nt = 0; nt < 8; nt++)
                    mma16816(sacc[nt], qf[kt], bfr[nt]);
            }

            // ---- causal mask ----
            const int r0 = wbase + gg, r1 = r0 + 8;
            if (j0 + 63 > wbase) {
                #pragma unroll
                for (int nt = 0; nt < 8; nt++) {
                    int c0 = j0 + nt * 8 + 2 * qt, c1 = c0 + 1;
                    if (c0 > r0) sacc[nt][0] = -1e30f;
                    if (c1 > r0) sacc[nt][1] = -1e30f;
                    if (c0 > r1) sacc[nt][2] = -1e30f;
                    if (c1 > r1) sacc[nt][3] = -1e30f;
                }
            }

            // ---- online softmax ----
            float mx0 = -1e30f, mx1 = -1e30f;
            #pragma unroll
            for (int nt = 0; nt < 8; nt++) {
                mx0 = fmaxf(mx0, fmaxf(sacc[nt][0], sacc[nt][1]));
                mx1 = fmaxf(mx1, fmaxf(sacc[nt][2], sacc[nt][3]));
            }
            mx0 = fmaxf(mx0, __shfl_xor_sync(0xffffffffu, mx0, 1));
            mx0 = fmaxf(mx0, __shfl_xor_sync(0xffffffffu, mx0, 2));
            mx1 = fmaxf(mx1, __shfl_xor_sync(0xffffffffu, mx1, 1));
            mx1 = fmaxf(mx1, __shfl_xor_sync(0xffffffffu, mx1, 2));
            float mn0 = fmaxf(m0, mx0), mn1 = fmaxf(m1, mx1);
            float cr0 = __expf(m0 - mn0), cr1 = __expf(m1 - mn1);
            m0 = mn0; m1 = mn1;

            float ps0 = 0.f, ps1 = 0.f;
            uint32_t pa[4][4];
            #pragma unroll
            for (int np = 0; np < 4; np++) {
                float e00 = __expf(sacc[2*np  ][0] - mn0);
                float e01 = __expf(sacc[2*np  ][1] - mn0);
                float e02 = __expf(sacc[2*np  ][2] - mn1);
                float e03 = __expf(sacc[2*np  ][3] - mn1);
                float e10 = __expf(sacc[2*np+1][0] - mn0);
                float e11 = __expf(sacc[2*np+1][1] - mn0);
                float e12 = __expf(sacc[2*np+1][2] - mn1);
                float e13 = __expf(sacc[2*np+1][3] - mn1);
                ps0 += e00 + e01 + e10 + e11;
                ps1 += e02 + e03 + e12 + e13;
                pa[np][0] = pk2(e00, e01);
                pa[np][1] = pk2(e02, e03);
                pa[np][2] = pk2(e10, e11);
                pa[np][3] = pk2(e12, e13);
            }
            ps0 += __shfl_xor_sync(0xffffffffu, ps0, 1);
            ps0 += __shfl_xor_sync(0xffffffffu, ps0, 2);
            ps1 += __shfl_xor_sync(0xffffffffu, ps1, 1);
            ps1 += __shfl_xor_sync(0xffffffffu, ps1, 2);
            l0 = l0 * cr0 + ps0;
            l1 = l1 * cr1 + ps1;
            #pragma unroll
            for (int nt = 0; nt < 8; nt++) {
                oacc[nt][0] *= cr0; oacc[nt][1] *= cr0;
                oacc[nt][2] *= cr1; oacc[nt][3] *= cr1;
            }

            // ---- O += P V ----
            #pragma unroll
            for (int kt = 0; kt < 4; kt++) {
                uint32_t vfr[8][2];
                #pragma unroll
                for (int np = 0; np < 4; np++) {
                    const bf16* p = &Vt[(kt * 16 + (g8 & 1) * 8 + lr) * KSTR + np * 16 + (g8 >> 1) * 8];
                    ldsm_x4_t(vfr[2*np][0], vfr[2*np][1], vfr[2*np+1][0], vfr[2*np+1][1], p);
                }
                #pragma unroll
                for (int nt = 0; nt < 8; nt++)
                    mma16816(oacc[nt], pa[kt], vfr[nt]);
            }
        }
        __syncthreads();
    }

    // ---- epilogue: normalize, split hi/lo, store ----
    float inv0 = 1.f / l0, inv1 = 1.f / l1;
    int grow0 = b * SEQ + wbase + gg;
    int grow1 = grow0 + 8;
    #pragma unroll
    for (int nt = 0; nt < 8; nt++) {
        int col = h * HDIM + nt * 8 + 2 * qt;
        float v00 = oacc[nt][0] * inv0, v01 = oacc[nt][1] * inv0;
        float v10 = oacc[nt][2] * inv1, v11 = oacc[nt][3] * inv1;
        bf16 h0,h1,h2,h3,l0b,l1b,l2b,l3b;
        split2(v00,h0,l0b); split2(v01,h1,l1b);
        split2(v10,h2,l2b); split2(v11,h3,l3b);
        bf162 pa; pa.x=h0; pa.y=h1;  bf162 pb; pb.x=h2; pb.y=h3;
        bf162 qa; qa.x=l0b; qa.y=l1b; bf162 qb; qb.x=l2b; qb.y=l3b;
        *(bf162*)(o_hi + (size_t)grow0 * DMODEL + col) = pa;
        *(bf162*)(o_hi + (size_t)grow1 * DMODEL + col) = pb;
        *(bf162*)(o_lo + (size_t)grow0 * DMODEL + col) = qa;
        *(bf162*)(o_lo + (size_t)grow1 * DMODEL + col) = qb;
    }
}

// ---------------- launch ----------------
extern "C" void kernel_launch(void* const* d_in, const int* in_sizes, int n_in,
                              void* d_out, int out_size)
{
    const float* x     = (const float*)d_in[0];
    const float* ln1_g = (const float*)d_in[1];
    const float* ln1_b = (const float*)d_in[2];
    const float* qkv_w = (const float*)d_in[3];
    const float* qkv_b = (const float*)d_in[4];
    const float* out_w = (const float*)d_in[5];
    const float* out_b = (const float*)d_in[6];
    const float* ln2_g = (const float*)d_in[7];
    const float* ln2_b = (const float*)d_in[8];
    const float* fc1_w = (const float*)d_in[9];
    const float* fc1_b = (const float*)d_in[10];
    const float* fc2_w = (const float*)d_in[11];
    const float* fc2_b = (const float*)d_in[12];
    float* out = (float*)d_out;

    static bf16 *p_qkvb = nullptr;
    static bf16 *p_h_hi, *p_h_lo, *p_o_hi, *p_o_lo, *p_h2_hi, *p_h2_lo;
    static bf16 *p_wqkv_hi, *p_wqkv_lo, *p_wout_hi, *p_wout_lo;
    static bf16 *p_wfc1_hi, *p_wfc1_lo, *p_wfc2_hi, *p_wfc2_lo;
    if (!p_qkvb) {
        cudaGetSymbolAddress((void**)&p_qkvb,   g_qkvb);
        cudaGetSymbolAddress((void**)&p_h_hi,   g_h_hi);
        cudaGetSymbolAddress((void**)&p_h_lo,   g_h_lo);
        cudaGetSymbolAddress((void**)&p_o_hi,   g_o_hi);
        cudaGetSymbolAddress((void**)&p_o_lo,   g_o_lo);
        cudaGetSymbolAddress((void**)&p_h2_hi,  g_h2_hi);
        cudaGetSymbolAddress((void**)&p_h2_lo,  g_h2_lo);
        cudaGetSymbolAddress((void**)&p_wqkv_hi, g_wqkv_hi);
        cudaGetSymbolAddress((void**)&p_wqkv_lo, g_wqkv_lo);
        cudaGetSymbolAddress((void**)&p_wout_hi, g_wout_hi);
        cudaGetSymbolAddress((void**)&p_wout_lo, g_wout_lo);
        cudaGetSymbolAddress((void**)&p_wfc1_hi, g_wfc1_hi);
        cudaGetSymbolAddress((void**)&p_wfc1_lo, g_wfc1_lo);
        cudaGetSymbolAddress((void**)&p_wfc2_hi, g_wfc2_hi);
        cudaGetSymbolAddress((void**)&p_wfc2_lo, g_wfc2_lo);
    }

    const int SMEM_GEMM = 2 * STAGE_B;                    // 81920
    const int SMEM_ATTN = (128 + 2*64 + 2*64) * KSTR * 2; // 55296
    cudaFuncSetAttribute(gemm_bf16x3<1>, cudaFuncAttributeMaxDynamicSharedMemorySize, SMEM_GEMM);
    cudaFuncSetAttribute(gemm_bf16x3<2>, cudaFuncAttributeMaxDynamicSharedMemorySize, SMEM_GEMM);
    cudaFuncSetAttribute(gemm_bf16x3<3>, cudaFuncAttributeMaxDynamicSharedMemorySize, SMEM_GEMM);
    cudaFuncSetAttribute(attn_mma_kernel, cudaFuncAttributeMaxDynamicSharedMemorySize, SMEM_ATTN);

    // weight splits
    split_kernel<<<(3*DMODEL*DMODEL)/4/256, 256>>>(qkv_w, p_wqkv_hi, p_wqkv_lo);
    split_kernel<<<(DMODEL*DMODEL)/4/256,   256>>>(out_w, p_wout_hi, p_wout_lo);
    split_kernel<<<(DFF*DMODEL)/4/256,      256>>>(fc1_w, p_wfc1_hi, p_wfc1_lo);
    split_kernel<<<(DMODEL*DFF)/4/256,      256>>>(fc2_w, p_wfc2_hi, p_wfc2_lo);

    // 1. h = LN1(x) -> split
    layernorm_split_kernel<<<MROWS, 256>>>(x, ln1_g, ln1_b, p_h_hi, p_h_lo);
    // 2. qkv = h @ qkv_w^T + qkv_b (bf16 out)
    gemm_bf16x3<3><<<dim3(3*DMODEL/BN, MROWS/BM), 256, SMEM_GEMM>>>(
        p_h_hi, p_h_lo, p_wqkv_hi, p_wqkv_lo, qkv_b, nullptr,
        nullptr, p_qkvb, nullptr, MROWS, 3*DMODEL, DMODEL);
    // 3. attention -> o split
    attn_mma_kernel<<<dim3(SEQ/128, BATCH*NHEADS), 256, SMEM_ATTN>>>(p_qkvb, p_o_hi, p_o_lo);
    // 4. out = x + o @ out_w^T + out_b
    gemm_bf16x3<2><<<dim3(DMODEL/BN, MROWS/BM), 256, SMEM_GEMM>>>(
        p_o_hi, p_o_lo, p_wout_hi, p_wout_lo, out_b, x,
        out, nullptr, nullptr, MROWS, DMODEL, DMODEL);
    // 5. h = LN2(out) -> split
    layernorm_split_kernel<<<MROWS, 256>>>(out, ln2_g, ln2_b, p_h_hi, p_h_lo);
    // 6. h2 = gelu(h @ fc1_w^T + fc1_b) -> split
    gemm_bf16x3<1><<<dim3(DFF/BN, MROWS/BM), 256, SMEM_GEMM>>>(
        p_h_hi, p_h_lo, p_wfc1_hi, p_wfc1_lo, fc1_b, nullptr,
        nullptr, p_h2_hi, p_h2_lo, MROWS, DFF, DMODEL);
    // 7. out = out + h2 @ fc2_w^T + fc2_b
    gemm_bf16x3<2><<<dim3(DMODEL/BN, MROWS/BM), 256, SMEM_GEMM>>>(
        p_h2_hi, p_h2_lo, p_wfc2_hi, p_wfc2_lo, fc2_b, out,
        out, nullptr, nullptr, MROWS, DMODEL, DFF);
}

// round 4
// speedup vs baseline: 4.2230x; 1.0275x over previous
#include <cuda_runtime.h>
#include <cuda_bf16.h>
#include <cstdint>
#include <cstddef>

// ---------------- problem constants ----------------
#define BATCH 4
#define SEQ   2048
#define DMODEL 1024
#define NHEADS 16
#define HDIM   64
#define DFF    4096
#define MROWS  (BATCH*SEQ)          // 8192
#define LN_EPS 1e-5f

typedef __nv_bfloat16  bf16;
typedef __nv_bfloat162 bf162;

// ---------------- scratch (device globals; no allocations allowed) ----------
__device__ bf16  g_qkvb[(size_t)MROWS * 3 * DMODEL];   // bf16 qkv for attention
__device__ bf16  g_h_hi[(size_t)MROWS * DMODEL];
__device__ bf16  g_h_lo[(size_t)MROWS * DMODEL];
__device__ bf16  g_o_hi[(size_t)MROWS * DMODEL];
__device__ bf16  g_o_lo[(size_t)MROWS * DMODEL];
__device__ bf16  g_h2_hi[(size_t)MROWS * DFF];
__device__ bf16  g_h2_lo[(size_t)MROWS * DFF];
__device__ bf16  g_wqkv_hi[(size_t)3*DMODEL*DMODEL];
__device__ bf16  g_wqkv_lo[(size_t)3*DMODEL*DMODEL];
__device__ bf16  g_wout_hi[(size_t)DMODEL*DMODEL];
__device__ bf16  g_wout_lo[(size_t)DMODEL*DMODEL];
__device__ bf16  g_wfc1_hi[(size_t)DFF*DMODEL];
__device__ bf16  g_wfc1_lo[(size_t)DFF*DMODEL];
__device__ bf16  g_wfc2_hi[(size_t)DMODEL*DFF];
__device__ bf16  g_wfc2_lo[(size_t)DMODEL*DFF];

// ---------------- helpers ----------------
__device__ __forceinline__ float gelu_exact(float x) {
    return 0.5f * x * (1.0f + erff(x * 0.70710678118654752f));
}
__device__ __forceinline__ void split2(float v, bf16& h, bf16& l) {
    h = __float2bfloat16(v);
    l = __float2bfloat16(v - __bfloat162float(h));
}
__device__ __forceinline__ uint32_t pk2(float a, float b) {
    bf162 t = __floats2bfloat162_rn(a, b);
    return *(uint32_t*)&t;
}
__device__ __forceinline__ void cp16(void* dst_smem, const void* src_gmem) {
    unsigned s = (unsigned)__cvta_generic_to_shared(dst_smem);
    asm volatile("cp.async.cg.shared.global [%0], [%1], 16;" :: "r"(s), "l"(src_gmem) : "memory");
}
__device__ __forceinline__ void cp_commit() {
    asm volatile("cp.async.commit_group;" ::: "memory");
}
template<int N>
__device__ __forceinline__ void cp_wait() {
    asm volatile("cp.async.wait_group %0;" :: "n"(N) : "memory");
}
__device__ __forceinline__ void mma16816(float* c, const uint32_t* a, const uint32_t* b) {
    asm volatile(
        "mma.sync.aligned.m16n8k16.row.col.f32.bf16.bf16.f32 "
        "{%0,%1,%2,%3}, {%4,%5,%6,%7}, {%8,%9}, {%0,%1,%2,%3};"
        : "+f"(c[0]), "+f"(c[1]), "+f"(c[2]), "+f"(c[3])
        : "r"(a[0]), "r"(a[1]), "r"(a[2]), "r"(a[3]), "r"(b[0]), "r"(b[1]));
}
__device__ __forceinline__ void ldsm_x4(uint32_t& r0, uint32_t& r1, uint32_t& r2, uint32_t& r3,
                                        const void* p) {
    uint32_t a = (uint32_t)__cvta_generic_to_shared(p);
    asm volatile("ldmatrix.sync.aligned.m8n8.x4.shared.b16 {%0,%1,%2,%3}, [%4];"
                 : "=r"(r0), "=r"(r1), "=r"(r2), "=r"(r3) : "r"(a));
}
__device__ __forceinline__ void ldsm_x4_t(uint32_t& r0, uint32_t& r1, uint32_t& r2, uint32_t& r3,
                                          const void* p) {
    uint32_t a = (uint32_t)__cvta_generic_to_shared(p);
    asm volatile("ldmatrix.sync.aligned.m8n8.x4.trans.shared.b16 {%0,%1,%2,%3}, [%4];"
                 : "=r"(r0), "=r"(r1), "=r"(r2), "=r"(r3) : "r"(a));
}

// ---------------- weight split kernel (fp32 -> bf16 hi/lo) -----------------
__global__ __launch_bounds__(256) void split_kernel(
    const float* __restrict__ in, bf16* __restrict__ hi, bf16* __restrict__ lo)
{
    int i = blockIdx.x * blockDim.x + threadIdx.x;
    float4 v = ((const float4*)in)[i];
    bf16 h0,h1,h2,h3,l0,l1,l2,l3;
    split2(v.x,h0,l0); split2(v.y,h1,l1); split2(v.z,h2,l2); split2(v.w,h3,l3);
    bf162 ha; ha.x=h0; ha.y=h1;  bf162 hb; hb.x=h2; hb.y=h3;
    bf162 la; la.x=l0; la.y=l1;  bf162 lb; lb.x=l2; lb.y=l3;
    ((bf162*)hi)[2*i]   = ha; ((bf162*)hi)[2*i+1] = hb;
    ((bf162*)lo)[2*i]   = la; ((bf162*)lo)[2*i+1] = lb;
}

// ---------------- LayerNorm -> split bf16 hi/lo ----------------------------
__global__ __launch_bounds__(256) void layernorm_split_kernel(
    const float* __restrict__ x, const float* __restrict__ g,
    const float* __restrict__ b, bf16* __restrict__ hi, bf16* __restrict__ lo)
{
    int row = blockIdx.x;
    const float4* xr = (const float4*)(x + (size_t)row * DMODEL);
    float4 v = xr[threadIdx.x];
    float s  = v.x + v.y + v.z + v.w;
    float sq = v.x*v.x + v.y*v.y + v.z*v.z + v.w*v.w;
    #pragma unroll
    for (int o = 16; o; o >>= 1) {
        s  += __shfl_xor_sync(0xffffffffu, s,  o);
        sq += __shfl_xor_sync(0xffffffffu, sq, o);
    }
    __shared__ float ss[8], ssq[8];
    int w = threadIdx.x >> 5, lane = threadIdx.x & 31;
    if (lane == 0) { ss[w] = s; ssq[w] = sq; }
    __syncthreads();
    float st = 0.f, sqt = 0.f;
    #pragma unroll
    for (int k = 0; k < 8; k++) { st += ss[k]; sqt += ssq[k]; }
    float mean = st * (1.0f / DMODEL);
    float var  = sqt * (1.0f / DMODEL) - mean * mean;
    float inv  = rsqrtf(var + LN_EPS);
    float4 gg = ((const float4*)g)[threadIdx.x];
    float4 bb = ((const float4*)b)[threadIdx.x];
    float o0 = (v.x - mean) * inv * gg.x + bb.x;
    float o1 = (v.y - mean) * inv * gg.y + bb.y;
    float o2 = (v.z - mean) * inv * gg.z + bb.z;
    float o3 = (v.w - mean) * inv * gg.w + bb.w;
    bf16 h0,h1,h2,h3,l0,l1,l2,l3;
    split2(o0,h0,l0); split2(o1,h1,l1); split2(o2,h2,l2); split2(o3,h3,l3);
    bf162 ha; ha.x=h0; ha.y=h1;  bf162 hb; hb.x=h2; hb.y=h3;
    bf162 la; la.x=l0; la.y=l1;  bf162 lb; lb.x=l2; lb.y=l3;
    bf162* hp = (bf162*)(hi + (size_t)row * DMODEL);
    bf162* lp = (bf162*)(lo + (size_t)row * DMODEL);
    hp[2*threadIdx.x] = ha; hp[2*threadIdx.x+1] = hb;
    lp[2*threadIdx.x] = la; lp[2*threadIdx.x+1] = lb;
}

// ---------------- bf16x3 tensor-core GEMM (ldmatrix mainloop) --------------
// MODE 1: gelu -> split bf16; MODE 2: fp32 bias+resid; MODE 3: bf16 out
#define BM 128
#define BN 128
#define BK 32
#define SSTRIDE 40
#define TILE_B  (BM * SSTRIDE * 2)
#define STAGE_B (4 * TILE_B)

template<int MODE>
__global__ __launch_bounds__(256, 2) void gemm_bf16x3(
    const bf16* __restrict__ Ah, const bf16* __restrict__ Al,
    const bf16* __restrict__ Bh, const bf16* __restrict__ Bl,
    const float* __restrict__ bias, const float* __restrict__ R,
    float* __restrict__ C, bf16* __restrict__ Chi, bf16* __restrict__ Clo,
    int M, int N, int K)
{
    extern __shared__ char smem[];
    const int tid  = threadIdx.x;
    const int bm = blockIdx.y * BM, bn = blockIdx.x * BN;
    const int warp = tid >> 5, lane = tid & 31;
    const int wm = warp >> 2, wn = warp & 3;
    const int gg = lane >> 2, qt = lane & 3;
    const int g8 = lane >> 3, lr = lane & 7;

    const bf16* gmat0 = Ah + (size_t)bm * K;
    const bf16* gmat1 = Al + (size_t)bm * K;
    const bf16* gmat2 = Bh + (size_t)bn * K;
    const bf16* gmat3 = Bl + (size_t)bn * K;

    float acc[4][4][4];
    #pragma unroll
    for (int i = 0; i < 4; i++)
        #pragma unroll
        for (int j = 0; j < 4; j++)
            #pragma unroll
            for (int q = 0; q < 4; q++) acc[i][j][q] = 0.f;

    const int NK = K / BK;

    auto issue = [&](int k0, int st) {
        char* sb = smem + st * STAGE_B;
        #pragma unroll
        for (int c = 0; c < 2; c++) {
            int chunk = tid + c * 256;
            int row = chunk >> 2, col = chunk & 3;
            size_t goff = (size_t)row * K + k0 + col * 8;
            char*  sdst = sb + row * (SSTRIDE * 2) + col * 16;
            cp16(sdst + 0 * TILE_B, gmat0 + goff);
            cp16(sdst + 1 * TILE_B, gmat1 + goff);
            cp16(sdst + 2 * TILE_B, gmat2 + goff);
            cp16(sdst + 3 * TILE_B, gmat3 + goff);
        }
    };

    issue(0, 0); cp_commit();

    // per-thread ldmatrix row offsets (in elements)
    const int a_row = (g8 & 1) * 8 + lr;        // within m16 tile
    const int a_col = (g8 >> 1) * 8;            // within k16 step
    const int b_row = (g8 >> 1) * 8 + lr;       // within n16 pair
    const int b_col = (g8 & 1) * 8;

    for (int ks = 0; ks < NK; ks++) {
        const int cur = ks & 1;
        if (ks + 1 < NK) { issue((ks + 1) * BK, cur ^ 1); cp_commit(); cp_wait<1>(); }
        else             { cp_wait<0>(); }
        __syncthreads();

        const bf16* sAh = (const bf16*)(smem + cur * STAGE_B);
        const bf16* sAl = sAh + BM * SSTRIDE;
        const bf16* sBh = sAl + BM * SSTRIDE;
        const bf16* sBl = sBh + BM * SSTRIDE;

        #pragma unroll
        for (int kk = 0; kk < BK; kk += 16) {
            uint32_t afr[4][4], bfr[4][2];
            // A-hi fragments: 4x ldmatrix.x4
            #pragma unroll
            for (int mt = 0; mt < 4; mt++) {
                const bf16* p = sAh + (wm*64 + mt*16 + a_row) * SSTRIDE + kk + a_col;
                ldsm_x4(afr[mt][0], afr[mt][1], afr[mt][2], afr[mt][3], p);
            }
            // B-hi fragments: 2x ldmatrix.x4 (each gives two n8 fragments)
            #pragma unroll
            for (int np = 0; np < 2; np++) {
                const bf16* p = sBh + (wn*32 + np*16 + b_row) * SSTRIDE + kk + b_col;
                ldsm_x4(bfr[2*np][0], bfr[2*np][1], bfr[2*np+1][0], bfr[2*np+1][1], p);
            }
            // Ah * Bh
            #pragma unroll
            for (int mt = 0; mt < 4; mt++)
                #pragma unroll
                for (int nt = 0; nt < 4; nt++)
                    mma16816(acc[mt][nt], afr[mt], bfr[nt]);
            // Al * Bh
            {
                uint32_t afl[4][4];
                #pragma unroll
                for (int mt = 0; mt < 4; mt++) {
                    const bf16* p = sAl + (wm*64 + mt*16 + a_row) * SSTRIDE + kk + a_col;
                    ldsm_x4(afl[mt][0], afl[mt][1], afl[mt][2], afl[mt][3], p);
                }
                #pragma unroll
                for (int mt = 0; mt < 4; mt++)
                    #pragma unroll
                    for (int nt = 0; nt < 4; nt++)
                        mma16816(acc[mt][nt], afl[mt], bfr[nt]);
            }
            // Ah * Bl (reuse bfr regs)
            #pragma unroll
            for (int np = 0; np < 2; np++) {
                const bf16* p = sBl + (wn*32 + np*16 + b_row) * SSTRIDE + kk + b_col;
                ldsm_x4(bfr[2*np][0], bfr[2*np][1], bfr[2*np+1][0], bfr[2*np+1][1], p);
            }
            #pragma unroll
            for (int mt = 0; mt < 4; mt++)
                #pragma unroll
                for (int nt = 0; nt < 4; nt++)
                    mma16816(acc[mt][nt], afr[mt], bfr[nt]);
        }
        __syncthreads();
    }

    #pragma unroll
    for (int mt = 0; mt < 4; mt++) {
        #pragma unroll
        for (int nt = 0; nt < 4; nt++) {
            int r  = bm + wm * 64 + mt * 16 + gg;
            int c0 = bn + wn * 32 + nt * 8 + 2 * qt;
            float2 bv = *(const float2*)(bias + c0);
            float v00 = acc[mt][nt][0] + bv.x;
            float v01 = acc[mt][nt][1] + bv.y;
            float v10 = acc[mt][nt][2] + bv.x;
            float v11 = acc[mt][nt][3] + bv.y;
            if (MODE == 2) {
                float2 r0 = *(const float2*)(R + (size_t)r * N + c0);
                float2 r1 = *(const float2*)(R + (size_t)(r + 8) * N + c0);
                v00 += r0.x; v01 += r0.y; v10 += r1.x; v11 += r1.y;
            }
            if (MODE == 1) {
                v00 = gelu_exact(v00); v01 = gelu_exact(v01);
                v10 = gelu_exact(v10); v11 = gelu_exact(v11);
                bf16 h0,h1,h2,h3,l0,l1,l2,l3;
                split2(v00,h0,l0); split2(v01,h1,l1);
                split2(v10,h2,l2); split2(v11,h3,l3);
                bf162 pa; pa.x=h0; pa.y=h1;  bf162 pb; pb.x=h2; pb.y=h3;
                bf162 qa; qa.x=l0; qa.y=l1;  bf162 qb; qb.x=l2; qb.y=l3;
                *(bf162*)(Chi + (size_t)r * N + c0)       = pa;
                *(bf162*)(Chi + (size_t)(r + 8) * N + c0) = pb;
                *(bf162*)(Clo + (size_t)r * N + c0)       = qa;
                *(bf162*)(Clo + (size_t)(r + 8) * N + c0) = qb;
            } else if (MODE == 3) {
                uint32_t pa = pk2(v00, v01);
                uint32_t pb = pk2(v10, v11);
                *(uint32_t*)(Chi + (size_t)r * N + c0)       = pa;
                *(uint32_t*)(Chi + (size_t)(r + 8) * N + c0) = pb;
            } else {
                *(float2*)(C + (size_t)r * N + c0)       = make_float2(v00, v01);
                *(float2*)(C + (size_t)(r + 8) * N + c0) = make_float2(v10, v11);
            }
        }
    }
}

// ---------------- tensor-core causal flash attention -----------------------
#define KSTR 72   // bf16 elems per smem row (64 data + 8 pad -> 144B stride)

__global__ __launch_bounds__(256) void attn_mma_kernel(
    const bf16* __restrict__ qkvb, bf16* __restrict__ o_hi, bf16* __restrict__ o_lo)
{
    extern __shared__ char asmem[];
    bf16* Qs = (bf16*)asmem;               // [128][KSTR]
    bf16* Ks = Qs + 128 * KSTR;            // [2][64][KSTR]
    bf16* Vs = Ks + 2 * 64 * KSTR;         // [2][64][KSTR]

    const int tid = threadIdx.x;
    const int warp = tid >> 5, lane = tid & 31;
    const int gg = lane >> 2, qt = lane & 3;
    const int g8 = lane >> 3, lr = lane & 7;
    const int qt_blk = blockIdx.x, bh = blockIdx.y;
    const int b = bh >> 4, h = bh & 15;
    const int q0 = qt_blk * 128;
    const size_t ROW = 3 * DMODEL;
    const bf16* qg = qkvb + (size_t)(b * SEQ) * ROW + h * HDIM;
    const bf16* kg = qg + DMODEL;
    const bf16* vg = qg + 2 * DMODEL;

    #pragma unroll
    for (int u = 0; u < 4; u++) {
        int idx = tid + u * 256;
        int r = idx >> 3, c = (idx & 7) * 8;
        *(uint4*)&Qs[r * KSTR + c] = *(const uint4*)(qg + (size_t)(q0 + r) * ROW + c);
    }
    __syncthreads();

    uint32_t qf[4][4];
    {
        const bf162 sc = __floats2bfloat162_rn(0.125f, 0.125f);
        #pragma unroll
        for (int kt = 0; kt < 4; kt++) {
            const bf16* p = &Qs[(warp * 16 + (g8 & 1) * 8 + lr) * KSTR + kt * 16 + (g8 >> 1) * 8];
            ldsm_x4(qf[kt][0], qf[kt][1], qf[kt][2], qf[kt][3], p);
            #pragma unroll
            for (int i = 0; i < 4; i++) {
                bf162 v = *(bf162*)&qf[kt][i];
                v = __hmul2(v, sc);
                qf[kt][i] = *(uint32_t*)&v;
            }
        }
    }

    float oacc[8][4];
    #pragma unroll
    for (int nt = 0; nt < 8; nt++)
        #pragma unroll
        for (int i = 0; i < 4; i++) oacc[nt][i] = 0.f;
    float m0 = -1e30f, m1 = -1e30f, l0 = 0.f, l1 = 0.f;

    const int ntiles = qt_blk * 2 + 2;
    const int wbase = q0 + warp * 16;
    const int wmax  = wbase + 15;

    auto issue = [&](int t, int st) {
        #pragma unroll
        for (int u = 0; u < 2; u++) {
            int idx = tid + u * 256;
            int r = idx >> 3, c = (idx & 7) * 8;
            size_t goff = (size_t)(t * 64 + r) * ROW + c;
            cp16(&Ks[st * 64 * KSTR + r * KSTR + c], kg + goff);
            cp16(&Vs[st * 64 * KSTR + r * KSTR + c], vg + goff);
        }
    };

    issue(0, 0); cp_commit();

    for (int t = 0; t < ntiles; t++) {
        const int cur = t & 1;
        if (t + 1 < ntiles) { issue(t + 1, cur ^ 1); cp_commit(); cp_wait<1>(); }
        else                { cp_wait<0>(); }
        __syncthreads();

        const int j0 = t * 64;
        if (j0 <= wmax) {
            const bf16* Kt = &Ks[cur * 64 * KSTR];
            const bf16* Vt = &Vs[cur * 64 * KSTR];

            float sacc[8][4];
            #pragma unroll
            for (int nt = 0; nt < 8; nt++)
                #pragma unroll
                for (int i = 0; i < 4; i++) sacc[nt][i] = 0.f;

            #pragma unroll
            for (int kt = 0; kt < 4; kt++) {
                uint32_t bfr[8][2];
                #pragma unroll
                for (int np = 0; np < 4; np++) {
                    const bf16* p = &Kt[(np * 16 + (g8 >> 1) * 8 + lr) * KSTR + kt * 16 + (g8 & 1) * 8];
                    ldsm_x4(bfr[2*np][0], bfr[2*np][1], bfr[2*np+1][0], bfr[2*np+1][1], p);
                }
                #pragma unroll
                for (int nt = 0; nt < 8; nt++)
                    mma16816(sacc[nt], qf[kt], bfr[nt]);
            }

            const int r0 = wbase + gg, r1 = r0 + 8;
            if (j0 + 63 > wbase) {
                #pragma unroll
                for (int nt = 0; nt < 8; nt++) {
                    int c0 = j0 + nt * 8 + 2 * qt, c1 = c0 + 1;
                    if (c0 > r0) sacc[nt][0] = -1e30f;
                    if (c1 > r0) sacc[nt][1] = -1e30f;
                    if (c0 > r1) sacc[nt][2] = -1e30f;
                    if (c1 > r1) sacc[nt][3] = -1e30f;
                }
            }

            float mx0 = -1e30f, mx1 = -1e30f;
            #pragma unroll
            for (int nt = 0; nt < 8; nt++) {
                mx0 = fmaxf(mx0, fmaxf(sacc[nt][0], sacc[nt][1]));
                mx1 = fmaxf(mx1, fmaxf(sacc[nt][2], sacc[nt][3]));
            }
            mx0 = fmaxf(mx0, __shfl_xor_sync(0xffffffffu, mx0, 1));
            mx0 = fmaxf(mx0, __shfl_xor_sync(0xffffffffu, mx0, 2));
            mx1 = fmaxf(mx1, __shfl_xor_sync(0xffffffffu, mx1, 1));
            mx1 = fmaxf(mx1, __shfl_xor_sync(0xffffffffu, mx1, 2));
            float mn0 = fmaxf(m0, mx0), mn1 = fmaxf(m1, mx1);
            float cr0 = __expf(m0 - mn0), cr1 = __expf(m1 - mn1);
            m0 = mn0; m1 = mn1;

            float ps0 = 0.f, ps1 = 0.f;
            uint32_t pa[4][4];
            #pragma unroll
            for (int np = 0; np < 4; np++) {
                float e00 = __expf(sacc[2*np  ][0] - mn0);
                float e01 = __expf(sacc[2*np  ][1] - mn0);
                float e02 = __expf(sacc[2*np  ][2] - mn1);
                float e03 = __expf(sacc[2*np  ][3] - mn1);
                float e10 = __expf(sacc[2*np+1][0] - mn0);
                float e11 = __expf(sacc[2*np+1][1] - mn0);
                float e12 = __expf(sacc[2*np+1][2] - mn1);
                float e13 = __expf(sacc[2*np+1][3] - mn1);
                ps0 += e00 + e01 + e10 + e11;
                ps1 += e02 + e03 + e12 + e13;
                pa[np][0] = pk2(e00, e01);
                pa[np][1] = pk2(e02, e03);
                pa[np][2] = pk2(e10, e11);
                pa[np][3] = pk2(e12, e13);
            }
            ps0 += __shfl_xor_sync(0xffffffffu, ps0, 1);
            ps0 += __shfl_xor_sync(0xffffffffu, ps0, 2);
            ps1 += __shfl_xor_sync(0xffffffffu, ps1, 1);
            ps1 += __shfl_xor_sync(0xffffffffu, ps1, 2);
            l0 = l0 * cr0 + ps0;
            l1 = l1 * cr1 + ps1;
            #pragma unroll
            for (int nt = 0; nt < 8; nt++) {
                oacc[nt][0] *= cr0; oacc[nt][1] *= cr0;
                oacc[nt][2] *= cr1; oacc[nt][3] *= cr1;
            }

            #pragma unroll
            for (int kt = 0; kt < 4; kt++) {
                uint32_t vfr[8][2];
                #pragma unroll
                for (int np = 0; np < 4; np++) {
                    const bf16* p = &Vt[(kt * 16 + (g8 & 1) * 8 + lr) * KSTR + np * 16 + (g8 >> 1) * 8];
                    ldsm_x4_t(vfr[2*np][0], vfr[2*np][1], vfr[2*np+1][0], vfr[2*np+1][1], p);
                }
                #pragma unroll
                for (int nt = 0; nt < 8; nt++)
                    mma16816(oacc[nt], pa[kt], vfr[nt]);
            }
        }
        __syncthreads();
    }

    float inv0 = 1.f / l0, inv1 = 1.f / l1;
    int grow0 = b * SEQ + wbase + gg;
    int grow1 = grow0 + 8;
    #pragma unroll
    for (int nt = 0; nt < 8; nt++) {
        int col = h * HDIM + nt * 8 + 2 * qt;
        float v00 = oacc[nt][0] * inv0, v01 = oacc[nt][1] * inv0;
        float v10 = oacc[nt][2] * inv1, v11 = oacc[nt][3] * inv1;
        bf16 h0,h1,h2,h3,l0b,l1b,l2b,l3b;
        split2(v00,h0,l0b); split2(v01,h1,l1b);
        split2(v10,h2,l2b); split2(v11,h3,l3b);
        bf162 pa; pa.x=h0; pa.y=h1;  bf162 pb; pb.x=h2; pb.y=h3;
        bf162 qa; qa.x=l0b; qa.y=l1b; bf162 qb; qb.x=l2b; qb.y=l3b;
        *(bf162*)(o_hi + (size_t)grow0 * DMODEL + col) = pa;
        *(bf162*)(o_hi + (size_t)grow1 * DMODEL + col) = pb;
        *(bf162*)(o_lo + (size_t)grow0 * DMODEL + col) = qa;
        *(bf162*)(o_lo + (size_t)grow1 * DMODEL + col) = qb;
    }
}

// ---------------- launch ----------------
extern "C" void kernel_launch(void* const* d_in, const int* in_sizes, int n_in,
                              void* d_out, int out_size)
{
    const float* x     = (const float*)d_in[0];
    const float* ln1_g = (const float*)d_in[1];
    const float* ln1_b = (const float*)d_in[2];
    const float* qkv_w = (const float*)d_in[3];
    const float* qkv_b = (const float*)d_in[4];
    const float* out_w = (const float*)d_in[5];
    const float* out_b = (const float*)d_in[6];
    const float* ln2_g = (const float*)d_in[7];
    const float* ln2_b = (const float*)d_in[8];
    const float* fc1_w = (const float*)d_in[9];
    const float* fc1_b = (const float*)d_in[10];
    const float* fc2_w = (const float*)d_in[11];
    const float* fc2_b = (const float*)d_in[12];
    float* out = (float*)d_out;

    static bf16 *p_qkvb = nullptr;
    static bf16 *p_h_hi, *p_h_lo, *p_o_hi, *p_o_lo, *p_h2_hi, *p_h2_lo;
    static bf16 *p_wqkv_hi, *p_wqkv_lo, *p_wout_hi, *p_wout_lo;
    static bf16 *p_wfc1_hi, *p_wfc1_lo, *p_wfc2_hi, *p_wfc2_lo;
    if (!p_qkvb) {
        cudaGetSymbolAddress((void**)&p_qkvb,   g_qkvb);
        cudaGetSymbolAddress((void**)&p_h_hi,   g_h_hi);
        cudaGetSymbolAddress((void**)&p_h_lo,   g_h_lo);
        cudaGetSymbolAddress((void**)&p_o_hi,   g_o_hi);
        cudaGetSymbolAddress((void**)&p_o_lo,   g_o_lo);
        cudaGetSymbolAddress((void**)&p_h2_hi,  g_h2_hi);
        cudaGetSymbolAddress((void**)&p_h2_lo,  g_h2_lo);
        cudaGetSymbolAddress((void**)&p_wqkv_hi, g_wqkv_hi);
        cudaGetSymbolAddress((void**)&p_wqkv_lo, g_wqkv_lo);
        cudaGetSymbolAddress((void**)&p_wout_hi, g_wout_hi);
        cudaGetSymbolAddress((void**)&p_wout_lo, g_wout_lo);
        cudaGetSymbolAddress((void**)&p_wfc1_hi, g_wfc1_hi);
        cudaGetSymbolAddress((void**)&p_wfc1_lo, g_wfc1_lo);
        cudaGetSymbolAddress((void**)&p_wfc2_hi, g_wfc2_hi);
        cudaGetSymbolAddress((void**)&p_wfc2_lo, g_wfc2_lo);
    }

    const int SMEM_GEMM = 2 * STAGE_B;                    // 81920
    const int SMEM_ATTN = (128 + 2*64 + 2*64) * KSTR * 2; // 55296
    cudaFuncSetAttribute(gemm_bf16x3<1>, cudaFuncAttributeMaxDynamicSharedMemorySize, SMEM_GEMM);
    cudaFuncSetAttribute(gemm_bf16x3<2>, cudaFuncAttributeMaxDynamicSharedMemorySize, SMEM_GEMM);
    cudaFuncSetAttribute(gemm_bf16x3<3>, cudaFuncAttributeMaxDynamicSharedMemorySize, SMEM_GEMM);
    cudaFuncSetAttribute(attn_mma_kernel, cudaFuncAttributeMaxDynamicSharedMemorySize, SMEM_ATTN);

    // weight splits
    split_kernel<<<(3*DMODEL*DMODEL)/4/256, 256>>>(qkv_w, p_wqkv_hi, p_wqkv_lo);
    split_kernel<<<(DMODEL*DMODEL)/4/256,   256>>>(out_w, p_wout_hi, p_wout_lo);
    split_kernel<<<(DFF*DMODEL)/4/256,      256>>>(fc1_w, p_wfc1_hi, p_wfc1_lo);
    split_kernel<<<(DMODEL*DFF)/4/256,      256>>>(fc2_w, p_wfc2_hi, p_wfc2_lo);

    // 1. h = LN1(x) -> split
    layernorm_split_kernel<<<MROWS, 256>>>(x, ln1_g, ln1_b, p_h_hi, p_h_lo);
    // 2. qkv = h @ qkv_w^T + qkv_b (bf16 out)
    gemm_bf16x3<3><<<dim3(3*DMODEL/BN, MROWS/BM), 256, SMEM_GEMM>>>(
        p_h_hi, p_h_lo, p_wqkv_hi, p_wqkv_lo, qkv_b, nullptr,
        nullptr, p_qkvb, nullptr, MROWS, 3*DMODEL, DMODEL);
    // 3. attention -> o split
    attn_mma_kernel<<<dim3(SEQ/128, BATCH*NHEADS), 256, SMEM_ATTN>>>(p_qkvb, p_o_hi, p_o_lo);
    // 4. out = x + o @ out_w^T + out_b
    gemm_bf16x3<2><<<dim3(DMODEL/BN, MROWS/BM), 256, SMEM_GEMM>>>(
        p_o_hi, p_o_lo, p_wout_hi, p_wout_lo, out_b, x,
        out, nullptr, nullptr, MROWS, DMODEL, DMODEL);
    // 5. h = LN2(out) -> split
    layernorm_split_kernel<<<MROWS, 256>>>(out, ln2_g, ln2_b, p_h_hi, p_h_lo);
    // 6. h2 = gelu(h @ fc1_w^T + fc1_b) -> split
    gemm_bf16x3<1><<<dim3(DFF/BN, MROWS/BM), 256, SMEM_GEMM>>>(
        p_h_hi, p_h_lo, p_wfc1_hi, p_wfc1_lo, fc1_b, nullptr,
        nullptr, p_h2_hi, p_h2_lo, MROWS, DFF, DMODEL);
    // 7. out = out + h2 @ fc2_w^T + fc2_b
    gemm_bf16x3<2><<<dim3(DMODEL/BN, MROWS/BM), 256, SMEM_GEMM>>>(
        p_h2_hi, p_h2_lo, p_wfc2_hi, p_wfc2_lo, fc2_b, out,
        out, nullptr, nullptr, MROWS, DMODEL, DFF);
}

// round 6
// speedup vs baseline: 4.4735x; 1.0593x over previous
#include <cuda_runtime.h>
#include <cuda_bf16.h>
#include <cstdint>
#include <cstddef>

// ---------------- problem constants ----------------
#define BATCH 4
#define SEQ   2048
#define DMODEL 1024
#define NHEADS 16
#define HDIM   64
#define DFF    4096
#define MROWS  (BATCH*SEQ)          // 8192
#define LN_EPS 1e-5f

typedef __nv_bfloat16  bf16;
typedef __nv_bfloat162 bf162;

// ---------------- scratch (device globals; no allocations allowed) ----------
__device__ bf16  g_qkvb[(size_t)MROWS * 3 * DMODEL];   // bf16 qkv for attention
__device__ bf16  g_h_hi[(size_t)MROWS * DMODEL];
__device__ bf16  g_h_lo[(size_t)MROWS * DMODEL];
__device__ bf16  g_o_hi[(size_t)MROWS * DMODEL];
__device__ bf16  g_o_lo[(size_t)MROWS * DMODEL];
__device__ bf16  g_h2_hi[(size_t)MROWS * DFF];
__device__ bf16  g_h2_lo[(size_t)MROWS * DFF];
__device__ bf16  g_wqkv_hi[(size_t)3*DMODEL*DMODEL];
__device__ bf16  g_wqkv_lo[(size_t)3*DMODEL*DMODEL];
__device__ bf16  g_wout_hi[(size_t)DMODEL*DMODEL];
__device__ bf16  g_wout_lo[(size_t)DMODEL*DMODEL];
__device__ bf16  g_wfc1_hi[(size_t)DFF*DMODEL];
__device__ bf16  g_wfc1_lo[(size_t)DFF*DMODEL];
__device__ bf16  g_wfc2_hi[(size_t)DMODEL*DFF];
__device__ bf16  g_wfc2_lo[(size_t)DMODEL*DFF];

// ---------------- helpers ----------------
__device__ __forceinline__ float gelu_exact(float x) {
    return 0.5f * x * (1.0f + erff(x * 0.70710678118654752f));
}
__device__ __forceinline__ void split2(float v, bf16& h, bf16& l) {
    h = __float2bfloat16(v);
    l = __float2bfloat16(v - __bfloat162float(h));
}
__device__ __forceinline__ uint32_t pk2(float a, float b) {
    bf162 t = __floats2bfloat162_rn(a, b);
    return *(uint32_t*)&t;
}
__device__ __forceinline__ void cp16(void* dst_smem, const void* src_gmem) {
    unsigned s = (unsigned)__cvta_generic_to_shared(dst_smem);
    asm volatile("cp.async.cg.shared.global [%0], [%1], 16;" :: "r"(s), "l"(src_gmem) : "memory");
}
__device__ __forceinline__ void cp_commit() {
    asm volatile("cp.async.commit_group;" ::: "memory");
}
template<int N>
__device__ __forceinline__ void cp_wait() {
    asm volatile("cp.async.wait_group %0;" :: "n"(N) : "memory");
}
__device__ __forceinline__ void mma16816(float* c, const uint32_t* a, const uint32_t* b) {
    asm volatile(
        "mma.sync.aligned.m16n8k16.row.col.f32.bf16.bf16.f32 "
        "{%0,%1,%2,%3}, {%4,%5,%6,%7}, {%8,%9}, {%0,%1,%2,%3};"
        : "+f"(c[0]), "+f"(c[1]), "+f"(c[2]), "+f"(c[3])
        : "r"(a[0]), "r"(a[1]), "r"(a[2]), "r"(a[3]), "r"(b[0]), "r"(b[1]));
}
__device__ __forceinline__ void ldsm_x4(uint32_t& r0, uint32_t& r1, uint32_t& r2, uint32_t& r3,
                                        const void* p) {
    uint32_t a = (uint32_t)__cvta_generic_to_shared(p);
    asm volatile("ldmatrix.sync.aligned.m8n8.x4.shared.b16 {%0,%1,%2,%3}, [%4];"
                 : "=r"(r0), "=r"(r1), "=r"(r2), "=r"(r3) : "r"(a));
}
__device__ __forceinline__ void ldsm_x4_t(uint32_t& r0, uint32_t& r1, uint32_t& r2, uint32_t& r3,
                                          const void* p) {
    uint32_t a = (uint32_t)__cvta_generic_to_shared(p);
    asm volatile("ldmatrix.sync.aligned.m8n8.x4.trans.shared.b16 {%0,%1,%2,%3}, [%4];"
                 : "=r"(r0), "=r"(r1), "=r"(r2), "=r"(r3) : "r"(a));
}

// ---------------- weight split kernel (fp32 -> bf16 hi/lo) -----------------
__global__ __launch_bounds__(256) void split_kernel(
    const float* __restrict__ in, bf16* __restrict__ hi, bf16* __restrict__ lo)
{
    int i = blockIdx.x * blockDim.x + threadIdx.x;
    float4 v = ((const float4*)in)[i];
    bf16 h0,h1,h2,h3,l0,l1,l2,l3;
    split2(v.x,h0,l0); split2(v.y,h1,l1); split2(v.z,h2,l2); split2(v.w,h3,l3);
    bf162 ha; ha.x=h0; ha.y=h1;  bf162 hb; hb.x=h2; hb.y=h3;
    bf162 la; la.x=l0; la.y=l1;  bf162 lb; lb.x=l2; lb.y=l3;
    ((bf162*)hi)[2*i]   = ha; ((bf162*)hi)[2*i+1] = hb;
    ((bf162*)lo)[2*i]   = la; ((bf162*)lo)[2*i+1] = lb;
}

// ---------------- LayerNorm -> split bf16 hi/lo ----------------------------
__global__ __launch_bounds__(256) void layernorm_split_kernel(
    const float* __restrict__ x, const float* __restrict__ g,
    const float* __restrict__ b, bf16* __restrict__ hi, bf16* __restrict__ lo)
{
    int row = blockIdx.x;
    const float4* xr = (const float4*)(x + (size_t)row * DMODEL);
    float4 v = xr[threadIdx.x];
    float s  = v.x + v.y + v.z + v.w;
    float sq = v.x*v.x + v.y*v.y + v.z*v.z + v.w*v.w;
    #pragma unroll
    for (int o = 16; o; o >>= 1) {
        s  += __shfl_xor_sync(0xffffffffu, s,  o);
        sq += __shfl_xor_sync(0xffffffffu, sq, o);
    }
    __shared__ float ss[8], ssq[8];
    int w = threadIdx.x >> 5, lane = threadIdx.x & 31;
    if (lane == 0) { ss[w] = s; ssq[w] = sq; }
    __syncthreads();
    float st = 0.f, sqt = 0.f;
    #pragma unroll
    for (int k = 0; k < 8; k++) { st += ss[k]; sqt += ssq[k]; }
    float mean = st * (1.0f / DMODEL);
    float var  = sqt * (1.0f / DMODEL) - mean * mean;
    float inv  = rsqrtf(var + LN_EPS);
    float4 gg = ((const float4*)g)[threadIdx.x];
    float4 bb = ((const float4*)b)[threadIdx.x];
    float o0 = (v.x - mean) * inv * gg.x + bb.x;
    float o1 = (v.y - mean) * inv * gg.y + bb.y;
    float o2 = (v.z - mean) * inv * gg.z + bb.z;
    float o3 = (v.w - mean) * inv * gg.w + bb.w;
    bf16 h0,h1,h2,h3,l0,l1,l2,l3;
    split2(o0,h0,l0); split2(o1,h1,l1); split2(o2,h2,l2); split2(o3,h3,l3);
    bf162 ha; ha.x=h0; ha.y=h1;  bf162 hb; hb.x=h2; hb.y=h3;
    bf162 la; la.x=l0; la.y=l1;  bf162 lb; lb.x=l2; lb.y=l3;
    bf162* hp = (bf162*)(hi + (size_t)row * DMODEL);
    bf162* lp = (bf162*)(lo + (size_t)row * DMODEL);
    hp[2*threadIdx.x] = ha; hp[2*threadIdx.x+1] = hb;
    lp[2*threadIdx.x] = la; lp[2*threadIdx.x+1] = lb;
}

// ---------------- bf16x3 tensor-core GEMM (ldmatrix mainloop) --------------
// MODE 1: gelu -> split bf16; MODE 2: fp32 bias+resid; MODE 3: bf16 out
// PASSES 3: Ah*Bh + Al*Bh + Ah*Bl;  PASSES 2: Ah*Bh + Al*Bh (Bl never loaded)
#define BM 128
#define BN 128
#define BK 32
#define SSTRIDE 40
#define TILE_B  (BM * SSTRIDE * 2)
#define STAGE_B (4 * TILE_B)

template<int MODE, int PASSES>
__global__ __launch_bounds__(256, 2) void gemm_bf16x3(
    const bf16* __restrict__ Ah, const bf16* __restrict__ Al,
    const bf16* __restrict__ Bh, const bf16* __restrict__ Bl,
    const float* __restrict__ bias, const float* __restrict__ R,
    float* __restrict__ C, bf16* __restrict__ Chi, bf16* __restrict__ Clo,
    int M, int N, int K)
{
    extern __shared__ char smem[];
    const int tid  = threadIdx.x;
    const int bm = blockIdx.y * BM, bn = blockIdx.x * BN;
    const int warp = tid >> 5, lane = tid & 31;
    const int wm = warp >> 2, wn = warp & 3;
    const int gg = lane >> 2, qt = lane & 3;
    const int g8 = lane >> 3, lr = lane & 7;

    const bf16* gmat0 = Ah + (size_t)bm * K;
    const bf16* gmat1 = Al + (size_t)bm * K;
    const bf16* gmat2 = Bh + (size_t)bn * K;
    const bf16* gmat3 = (PASSES == 3) ? (Bl + (size_t)bn * K) : nullptr;

    float acc[4][4][4];
    #pragma unroll
    for (int i = 0; i < 4; i++)
        #pragma unroll
        for (int j = 0; j < 4; j++)
            #pragma unroll
            for (int q = 0; q < 4; q++) acc[i][j][q] = 0.f;

    const int NK = K / BK;

    auto issue = [&](int k0, int st) {
        char* sb = smem + st * STAGE_B;
        #pragma unroll
        for (int c = 0; c < 2; c++) {
            int chunk = tid + c * 256;
            int row = chunk >> 2, col = chunk & 3;
            size_t goff = (size_t)row * K + k0 + col * 8;
            char*  sdst = sb + row * (SSTRIDE * 2) + col * 16;
            cp16(sdst + 0 * TILE_B, gmat0 + goff);
            cp16(sdst + 1 * TILE_B, gmat1 + goff);
            cp16(sdst + 2 * TILE_B, gmat2 + goff);
            if (PASSES == 3) cp16(sdst + 3 * TILE_B, gmat3 + goff);
        }
    };

    issue(0, 0); cp_commit();

    const int a_row = (g8 & 1) * 8 + lr;
    const int a_col = (g8 >> 1) * 8;
    const int b_row = (g8 >> 1) * 8 + lr;
    const int b_col = (g8 & 1) * 8;

    for (int ks = 0; ks < NK; ks++) {
        const int cur = ks & 1;
        if (ks + 1 < NK) { issue((ks + 1) * BK, cur ^ 1); cp_commit(); cp_wait<1>(); }
        else             { cp_wait<0>(); }
        __syncthreads();

        const bf16* sAh = (const bf16*)(smem + cur * STAGE_B);
        const bf16* sAl = sAh + BM * SSTRIDE;
        const bf16* sBh = sAl + BM * SSTRIDE;
        const bf16* sBl = sBh + BM * SSTRIDE;

        #pragma unroll
        for (int kk = 0; kk < BK; kk += 16) {
            uint32_t afr[4][4], bfr[4][2];
            #pragma unroll
            for (int mt = 0; mt < 4; mt++) {
                const bf16* p = sAh + (wm*64 + mt*16 + a_row) * SSTRIDE + kk + a_col;
                ldsm_x4(afr[mt][0], afr[mt][1], afr[mt][2], afr[mt][3], p);
            }
            #pragma unroll
            for (int np = 0; np < 2; np++) {
                const bf16* p = sBh + (wn*32 + np*16 + b_row) * SSTRIDE + kk + b_col;
                ldsm_x4(bfr[2*np][0], bfr[2*np][1], bfr[2*np+1][0], bfr[2*np+1][1], p);
            }
            // Ah * Bh
            #pragma unroll
            for (int mt = 0; mt < 4; mt++)
                #pragma unroll
                for (int nt = 0; nt < 4; nt++)
                    mma16816(acc[mt][nt], afr[mt], bfr[nt]);
            // Al * Bh
            {
                uint32_t afl[4][4];
                #pragma unroll
                for (int mt = 0; mt < 4; mt++) {
                    const bf16* p = sAl + (wm*64 + mt*16 + a_row) * SSTRIDE + kk + a_col;
                    ldsm_x4(afl[mt][0], afl[mt][1], afl[mt][2], afl[mt][3], p);
                }
                #pragma unroll
                for (int mt = 0; mt < 4; mt++)
                    #pragma unroll
                    for (int nt = 0; nt < 4; nt++)
                        mma16816(acc[mt][nt], afl[mt], bfr[nt]);
            }
            // Ah * Bl (pass 3 only)
            if (PASSES == 3) {
                #pragma unroll
                for (int np = 0; np < 2; np++) {
                    const bf16* p = sBl + (wn*32 + np*16 + b_row) * SSTRIDE + kk + b_col;
                    ldsm_x4(bfr[2*np][0], bfr[2*np][1], bfr[2*np+1][0], bfr[2*np+1][1], p);
                }
                #pragma unroll
                for (int mt = 0; mt < 4; mt++)
                    #pragma unroll
                    for (int nt = 0; nt < 4; nt++)
                        mma16816(acc[mt][nt], afr[mt], bfr[nt]);
            }
        }
        __syncthreads();
    }

    #pragma unroll
    for (int mt = 0; mt < 4; mt++) {
        #pragma unroll
        for (int nt = 0; nt < 4; nt++) {
            int r  = bm + wm * 64 + mt * 16 + gg;
            int c0 = bn + wn * 32 + nt * 8 + 2 * qt;
            float2 bv = *(const float2*)(bias + c0);
            float v00 = acc[mt][nt][0] + bv.x;
            float v01 = acc[mt][nt][1] + bv.y;
            float v10 = acc[mt][nt][2] + bv.x;
            float v11 = acc[mt][nt][3] + bv.y;
            if (MODE == 2) {
                float2 r0 = *(const float2*)(R + (size_t)r * N + c0);
                float2 r1 = *(const float2*)(R + (size_t)(r + 8) * N + c0);
                v00 += r0.x; v01 += r0.y; v10 += r1.x; v11 += r1.y;
            }
            if (MODE == 1) {
                v00 = gelu_exact(v00); v01 = gelu_exact(v01);
                v10 = gelu_exact(v10); v11 = gelu_exact(v11);
                bf16 h0,h1,h2,h3,l0,l1,l2,l3;
                split2(v00,h0,l0); split2(v01,h1,l1);
                split2(v10,h2,l2); split2(v11,h3,l3);
                bf162 pa; pa.x=h0; pa.y=h1;  bf162 pb; pb.x=h2; pb.y=h3;
                bf162 qa; qa.x=l0; qa.y=l1;  bf162 qb; qb.x=l2; qb.y=l3;
                *(bf162*)(Chi + (size_t)r * N + c0)       = pa;
                *(bf162*)(Chi + (size_t)(r + 8) * N + c0) = pb;
                *(bf162*)(Clo + (size_t)r * N + c0)       = qa;
                *(bf162*)(Clo + (size_t)(r + 8) * N + c0) = qb;
            } else if (MODE == 3) {
                uint32_t pa = pk2(v00, v01);
                uint32_t pb = pk2(v10, v11);
                *(uint32_t*)(Chi + (size_t)r * N + c0)       = pa;
                *(uint32_t*)(Chi + (size_t)(r + 8) * N + c0) = pb;
            } else {
                *(float2*)(C + (size_t)r * N + c0)       = make_float2(v00, v01);
                *(float2*)(C + (size_t)(r + 8) * N + c0) = make_float2(v10, v11);
            }
        }
    }
}

// ---------------- tensor-core causal flash attention -----------------------
#define KSTR 72   // bf16 elems per smem row (64 data + 8 pad -> 144B stride)

__global__ __launch_bounds__(256) void attn_mma_kernel(
    const bf16* __restrict__ qkvb, bf16* __restrict__ o_hi, bf16* __restrict__ o_lo)
{
    extern __shared__ char asmem[];
    bf16* Qs = (bf16*)asmem;
    bf16* Ks = Qs + 128 * KSTR;
    bf16* Vs = Ks + 2 * 64 * KSTR;

    const int tid = threadIdx.x;
    const int warp = tid >> 5, lane = tid & 31;
    const int gg = lane >> 2, qt = lane & 3;
    const int g8 = lane >> 3, lr = lane & 7;
    const int qt_blk = blockIdx.x, bh = blockIdx.y;
    const int b = bh >> 4, h = bh & 15;
    const int q0 = qt_blk * 128;
    const size_t ROW = 3 * DMODEL;
    const bf16* qg = qkvb + (size_t)(b * SEQ) * ROW + h * HDIM;
    const bf16* kg = qg + DMODEL;
    const bf16* vg = qg + 2 * DMODEL;

    #pragma unroll
    for (int u = 0; u < 4; u++) {
        int idx = tid + u * 256;
        int r = idx >> 3, c = (idx & 7) * 8;
        *(uint4*)&Qs[r * KSTR + c] = *(const uint4*)(qg + (size_t)(q0 + r) * ROW + c);
    }
    __syncthreads();

    uint32_t qf[4][4];
    {
        const bf162 sc = __floats2bfloat162_rn(0.125f, 0.125f);
        #pragma unroll
        for (int kt = 0; kt < 4; kt++) {
            const bf16* p = &Qs[(warp * 16 + (g8 & 1) * 8 + lr) * KSTR + kt * 16 + (g8 >> 1) * 8];
            ldsm_x4(qf[kt][0], qf[kt][1], qf[kt][2], qf[kt][3], p);
            #pragma unroll
            for (int i = 0; i < 4; i++) {
                bf162 v = *(bf162*)&qf[kt][i];
                v = __hmul2(v, sc);
                qf[kt][i] = *(uint32_t*)&v;
            }
        }
    }

    float oacc[8][4];
    #pragma unroll
    for (int nt = 0; nt < 8; nt++)
        #pragma unroll
        for (int i = 0; i < 4; i++) oacc[nt][i] = 0.f;
    float m0 = -1e30f, m1 = -1e30f, l0 = 0.f, l1 = 0.f;

    const int ntiles = qt_blk * 2 + 2;
    const int wbase = q0 + warp * 16;
    const int wmax  = wbase + 15;

    auto issue = [&](int t, int st) {
        #pragma unroll
        for (int u = 0; u < 2; u++) {
            int idx = tid + u * 256;
            int r = idx >> 3, c = (idx & 7) * 8;
            size_t goff = (size_t)(t * 64 + r) * ROW + c;
            cp16(&Ks[st * 64 * KSTR + r * KSTR + c], kg + goff);
            cp16(&Vs[st * 64 * KSTR + r * KSTR + c], vg + goff);
        }
    };

    issue(0, 0); cp_commit();

    for (int t = 0; t < ntiles; t++) {
        const int cur = t & 1;
        if (t + 1 < ntiles) { issue(t + 1, cur ^ 1); cp_commit(); cp_wait<1>(); }
        else                { cp_wait<0>(); }
        __syncthreads();

        const int j0 = t * 64;
        if (j0 <= wmax) {
            const bf16* Kt = &Ks[cur * 64 * KSTR];
            const bf16* Vt = &Vs[cur * 64 * KSTR];

            float sacc[8][4];
            #pragma unroll
            for (int nt = 0; nt < 8; nt++)
                #pragma unroll
                for (int i = 0; i < 4; i++) sacc[nt][i] = 0.f;

            #pragma unroll
            for (int kt = 0; kt < 4; kt++) {
                uint32_t bfr[8][2];
                #pragma unroll
                for (int np = 0; np < 4; np++) {
                    const bf16* p = &Kt[(np * 16 + (g8 >> 1) * 8 + lr) * KSTR + kt * 16 + (g8 & 1) * 8];
                    ldsm_x4(bfr[2*np][0], bfr[2*np][1], bfr[2*np+1][0], bfr[2*np+1][1], p);
                }
                #pragma unroll
                for (int nt = 0; nt < 8; nt++)
                    mma16816(sacc[nt], qf[kt], bfr[nt]);
            }

            const int r0 = wbase + gg, r1 = r0 + 8;
            if (j0 + 63 > wbase) {
                #pragma unroll
                for (int nt = 0; nt < 8; nt++) {
                    int c0 = j0 + nt * 8 + 2 * qt, c1 = c0 + 1;
                    if (c0 > r0) sacc[nt][0] = -1e30f;
                    if (c1 > r0) sacc[nt][1] = -1e30f;
                    if (c0 > r1) sacc[nt][2] = -1e30f;
                    if (c1 > r1) sacc[nt][3] = -1e30f;
                }
            }

            float mx0 = -1e30f, mx1 = -1e30f;
            #pragma unroll
            for (int nt = 0; nt < 8; nt++) {
                mx0 = fmaxf(mx0, fmaxf(sacc[nt][0], sacc[nt][1]));
                mx1 = fmaxf(mx1, fmaxf(sacc[nt][2], sacc[nt][3]));
            }
            mx0 = fmaxf(mx0, __shfl_xor_sync(0xffffffffu, mx0, 1));
            mx0 = fmaxf(mx0, __shfl_xor_sync(0xffffffffu, mx0, 2));
            mx1 = fmaxf(mx1, __shfl_xor_sync(0xffffffffu, mx1, 1));
            mx1 = fmaxf(mx1, __shfl_xor_sync(0xffffffffu, mx1, 2));
            float mn0 = fmaxf(m0, mx0), mn1 = fmaxf(m1, mx1);
            float cr0 = __expf(m0 - mn0), cr1 = __expf(m1 - mn1);
            m0 = mn0; m1 = mn1;

            float ps0 = 0.f, ps1 = 0.f;
            uint32_t pa[4][4];
            #pragma unroll
            for (int np = 0; np < 4; np++) {
                float e00 = __expf(sacc[2*np  ][0] - mn0);
                float e01 = __expf(sacc[2*np  ][1] - mn0);
                float e02 = __expf(sacc[2*np  ][2] - mn1);
                float e03 = __expf(sacc[2*np  ][3] - mn1);
                float e10 = __expf(sacc[2*np+1][0] - mn0);
                float e11 = __expf(sacc[2*np+1][1] - mn0);
                float e12 = __expf(sacc[2*np+1][2] - mn1);
                float e13 = __expf(sacc[2*np+1][3] - mn1);
                ps0 += e00 + e01 + e10 + e11;
                ps1 += e02 + e03 + e12 + e13;
                pa[np][0] = pk2(e00, e01);
                pa[np][1] = pk2(e02, e03);
                pa[np][2] = pk2(e10, e11);
                pa[np][3] = pk2(e12, e13);
            }
            ps0 += __shfl_xor_sync(0xffffffffu, ps0, 1);
            ps0 += __shfl_xor_sync(0xffffffffu, ps0, 2);
            ps1 += __shfl_xor_sync(0xffffffffu, ps1, 1);
            ps1 += __shfl_xor_sync(0xffffffffu, ps1, 2);
            l0 = l0 * cr0 + ps0;
            l1 = l1 * cr1 + ps1;
            #pragma unroll
            for (int nt = 0; nt < 8; nt++) {
                oacc[nt][0] *= cr0; oacc[nt][1] *= cr0;
                oacc[nt][2] *= cr1; oacc[nt][3] *= cr1;
            }

            #pragma unroll
            for (int kt = 0; kt < 4; kt++) {
                uint32_t vfr[8][2];
                #pragma unroll
                for (int np = 0; np < 4; np++) {
                    const bf16* p = &Vt[(kt * 16 + (g8 & 1) * 8 + lr) * KSTR + np * 16 + (g8 >> 1) * 8];
                    ldsm_x4_t(vfr[2*np][0], vfr[2*np][1], vfr[2*np+1][0], vfr[2*np+1][1], p);
                }
                #pragma unroll
                for (int nt = 0; nt < 8; nt++)
                    mma16816(oacc[nt], pa[kt], vfr[nt]);
            }
        }
        __syncthreads();
    }

    float inv0 = 1.f / l0, inv1 = 1.f / l1;
    int grow0 = b * SEQ + wbase + gg;
    int grow1 = grow0 + 8;
    #pragma unroll
    for (int nt = 0; nt < 8; nt++) {
        int col = h * HDIM + nt * 8 + 2 * qt;
        float v00 = oacc[nt][0] * inv0, v01 = oacc[nt][1] * inv0;
        float v10 = oacc[nt][2] * inv1, v11 = oacc[nt][3] * inv1;
        bf16 h0,h1,h2,h3,l0b,l1b,l2b,l3b;
        split2(v00,h0,l0b); split2(v01,h1,l1b);
        split2(v10,h2,l2b); split2(v11,h3,l3b);
        bf162 pa; pa.x=h0; pa.y=h1;  bf162 pb; pb.x=h2; pb.y=h3;
        bf162 qa; qa.x=l0b; qa.y=l1b; bf162 qb; qb.x=l2b; qb.y=l3b;
        *(bf162*)(o_hi + (size_t)grow0 * DMODEL + col) = pa;
        *(bf162*)(o_hi + (size_t)grow1 * DMODEL + col) = pb;
        *(bf162*)(o_lo + (size_t)grow0 * DMODEL + col) = qa;
        *(bf162*)(o_lo + (size_t)grow1 * DMODEL + col) = qb;
    }
}

// ---------------- launch ----------------
extern "C" void kernel_launch(void* const* d_in, const int* in_sizes, int n_in,
                              void* d_out, int out_size)
{
    const float* x     = (const float*)d_in[0];
    const float* ln1_g = (const float*)d_in[1];
    const float* ln1_b = (const float*)d_in[2];
    const float* qkv_w = (const float*)d_in[3];
    const float* qkv_b = (const float*)d_in[4];
    const float* out_w = (const float*)d_in[5];
    const float* out_b = (const float*)d_in[6];
    const float* ln2_g = (const float*)d_in[7];
    const float* ln2_b = (const float*)d_in[8];
    const float* fc1_w = (const float*)d_in[9];
    const float* fc1_b = (const float*)d_in[10];
    const float* fc2_w = (const float*)d_in[11];
    const float* fc2_b = (const float*)d_in[12];
    float* out = (float*)d_out;

    static bf16 *p_qkvb = nullptr;
    static bf16 *p_h_hi, *p_h_lo, *p_o_hi, *p_o_lo, *p_h2_hi, *p_h2_lo;
    static bf16 *p_wqkv_hi, *p_wqkv_lo, *p_wout_hi, *p_wout_lo;
    static bf16 *p_wfc1_hi, *p_wfc1_lo, *p_wfc2_hi, *p_wfc2_lo;
    if (!p_qkvb) {
        cudaGetSymbolAddress((void**)&p_qkvb,   g_qkvb);
        cudaGetSymbolAddress((void**)&p_h_hi,   g_h_hi);
        cudaGetSymbolAddress((void**)&p_h_lo,   g_h_lo);
        cudaGetSymbolAddress((void**)&p_o_hi,   g_o_hi);
        cudaGetSymbolAddress((void**)&p_o_lo,   g_o_lo);
        cudaGetSymbolAddress((void**)&p_h2_hi,  g_h2_hi);
        cudaGetSymbolAddress((void**)&p_h2_lo,  g_h2_lo);
        cudaGetSymbolAddress((void**)&p_wqkv_hi, g_wqkv_hi);
        cudaGetSymbolAddress((void**)&p_wqkv_lo, g_wqkv_lo);
        cudaGetSymbolAddress((void**)&p_wout_hi, g_wout_hi);
        cudaGetSymbolAddress((void**)&p_wout_lo, g_wout_lo);
        cudaGetSymbolAddress((void**)&p_wfc1_hi, g_wfc1_hi);
        cudaGetSymbolAddress((void**)&p_wfc1_lo, g_wfc1_lo);
        cudaGetSymbolAddress((void**)&p_wfc2_hi, g_wfc2_hi);
        cudaGetSymbolAddress((void**)&p_wfc2_lo, g_wfc2_lo);
    }

    const int SMEM_GEMM = 2 * STAGE_B;                    // 81920
    const int SMEM_ATTN = (128 + 2*64 + 2*64) * KSTR * 2; // 55296
    cudaFuncSetAttribute((const void*)gemm_bf16x3<1,3>, cudaFuncAttributeMaxDynamicSharedMemorySize, SMEM_GEMM);
    cudaFuncSetAttribute((const void*)gemm_bf16x3<2,3>, cudaFuncAttributeMaxDynamicSharedMemorySize, SMEM_GEMM);
    cudaFuncSetAttribute((const void*)gemm_bf16x3<3,2>, cudaFuncAttributeMaxDynamicSharedMemorySize, SMEM_GEMM);
    cudaFuncSetAttribute((const void*)attn_mma_kernel,  cudaFuncAttributeMaxDynamicSharedMemorySize, SMEM_ATTN);

    // weight splits
    split_kernel<<<(3*DMODEL*DMODEL)/4/256, 256>>>(qkv_w, p_wqkv_hi, p_wqkv_lo);
    split_kernel<<<(DMODEL*DMODEL)/4/256,   256>>>(out_w, p_wout_hi, p_wout_lo);
    split_kernel<<<(DFF*DMODEL)/4/256,      256>>>(fc1_w, p_wfc1_hi, p_wfc1_lo);
    split_kernel<<<(DMODEL*DFF)/4/256,      256>>>(fc2_w, p_wfc2_hi, p_wfc2_lo);

    // 1. h = LN1(x) -> split
    layernorm_split_kernel<<<MROWS, 256>>>(x, ln1_g, ln1_b, p_h_hi, p_h_lo);
    // 2. qkv = h @ qkv_w^T + qkv_b (bf16 out; 2-pass — output is bf16-rounded anyway)
    gemm_bf16x3<3,2><<<dim3(3*DMODEL/BN, MROWS/BM), 256, SMEM_GEMM>>>(
        p_h_hi, p_h_lo, p_wqkv_hi, p_wqkv_lo, qkv_b, nullptr,
        nullptr, p_qkvb, nullptr, MROWS, 3*DMODEL, DMODEL);
    // 3. attention -> o split
    attn_mma_kernel<<<dim3(SEQ/128, BATCH*NHEADS), 256, SMEM_ATTN>>>(p_qkvb, p_o_hi, p_o_lo);
    // 4. out = x + o @ out_w^T + out_b  (3-pass)
    gemm_bf16x3<2,3><<<dim3(DMODEL/BN, MROWS/BM), 256, SMEM_GEMM>>>(
        p_o_hi, p_o_lo, p_wout_hi, p_wout_lo, out_b, x,
        out, nullptr, nullptr, MROWS, DMODEL, DMODEL);
    // 5. h = LN2(out) -> split
    layernorm_split_kernel<<<MROWS, 256>>>(out, ln2_g, ln2_b, p_h_hi, p_h_lo);
    // 6. h2 = gelu(h @ fc1_w^T + fc1_b) -> split  (3-pass)
    gemm_bf16x3<1,3><<<dim3(DFF/BN, MROWS/BM), 256, SMEM_GEMM>>>(
        p_h_hi, p_h_lo, p_wfc1_hi, p_wfc1_lo, fc1_b, nullptr,
        nullptr, p_h2_hi, p_h2_lo, MROWS, DFF, DMODEL);
    // 7. out = out + h2 @ fc2_w^T + fc2_b  (3-pass)
    gemm_bf16x3<2,3><<<dim3(DMODEL/BN, MROWS/BM), 256, SMEM_GEMM>>>(
        p_h2_hi, p_h2_lo, p_wfc2_hi, p_wfc2_lo, fc2_b, out,
        out, nullptr, nullptr, MROWS, DMODEL, DFF);
}

// round 8
// speedup vs baseline: 4.9276x; 1.1015x over previous
#include <cuda_runtime.h>
#include <cuda_bf16.h>
#include <cstdint>
#include <cstddef>

// ---------------- problem constants ----------------
#define BATCH 4
#define SEQ   2048
#define DMODEL 1024
#define NHEADS 16
#define HDIM   64
#define DFF    4096
#define MROWS  (BATCH*SEQ)          // 8192
#define LN_EPS 1e-5f

typedef __nv_bfloat16  bf16;
typedef __nv_bfloat162 bf162;

// ---------------- scratch (device globals; no allocations allowed) ----------
__device__ bf16  g_qkvb[(size_t)MROWS * 3 * DMODEL];   // bf16 qkv for attention
__device__ bf16  g_h_hi[(size_t)MROWS * DMODEL];
__device__ bf16  g_h_lo[(size_t)MROWS * DMODEL];
__device__ bf16  g_o_hi[(size_t)MROWS * DMODEL];
__device__ bf16  g_o_lo[(size_t)MROWS * DMODEL];
__device__ bf16  g_h2_hi[(size_t)MROWS * DFF];
__device__ bf16  g_h2_lo[(size_t)MROWS * DFF];
__device__ bf16  g_wqkv_hi[(size_t)3*DMODEL*DMODEL];
__device__ bf16  g_wqkv_lo[(size_t)3*DMODEL*DMODEL];
__device__ bf16  g_wout_hi[(size_t)DMODEL*DMODEL];
__device__ bf16  g_wout_lo[(size_t)DMODEL*DMODEL];
__device__ bf16  g_wfc1_hi[(size_t)DFF*DMODEL];
__device__ bf16  g_wfc1_lo[(size_t)DFF*DMODEL];
__device__ bf16  g_wfc2_hi[(size_t)DMODEL*DFF];
__device__ bf16  g_wfc2_lo[(size_t)DMODEL*DFF];

// ---------------- helpers ----------------
__device__ __forceinline__ float gelu_exact(float x) {
    return 0.5f * x * (1.0f + erff(x * 0.70710678118654752f));
}
__device__ __forceinline__ void split2(float v, bf16& h, bf16& l) {
    h = __float2bfloat16(v);
    l = __float2bfloat16(v - __bfloat162float(h));
}
__device__ __forceinline__ uint32_t pk2(float a, float b) {
    bf162 t = __floats2bfloat162_rn(a, b);
    return *(uint32_t*)&t;
}
__device__ __forceinline__ void cp16(void* dst_smem, const void* src_gmem) {
    unsigned s = (unsigned)__cvta_generic_to_shared(dst_smem);
    asm volatile("cp.async.cg.shared.global [%0], [%1], 16;" :: "r"(s), "l"(src_gmem) : "memory");
}
__device__ __forceinline__ void cp_commit() {
    asm volatile("cp.async.commit_group;" ::: "memory");
}
template<int N>
__device__ __forceinline__ void cp_wait() {
    asm volatile("cp.async.wait_group %0;" :: "n"(N) : "memory");
}
__device__ __forceinline__ void mma16816(float* c, const uint32_t* a, const uint32_t* b) {
    asm volatile(
        "mma.sync.aligned.m16n8k16.row.col.f32.bf16.bf16.f32 "
        "{%0,%1,%2,%3}, {%4,%5,%6,%7}, {%8,%9}, {%0,%1,%2,%3};"
        : "+f"(c[0]), "+f"(c[1]), "+f"(c[2]), "+f"(c[3])
        : "r"(a[0]), "r"(a[1]), "r"(a[2]), "r"(a[3]), "r"(b[0]), "r"(b[1]));
}
__device__ __forceinline__ void ldsm_x4(uint32_t& r0, uint32_t& r1, uint32_t& r2, uint32_t& r3,
                                        const void* p) {
    uint32_t a = (uint32_t)__cvta_generic_to_shared(p);
    asm volatile("ldmatrix.sync.aligned.m8n8.x4.shared.b16 {%0,%1,%2,%3}, [%4];"
                 : "=r"(r0), "=r"(r1), "=r"(r2), "=r"(r3) : "r"(a));
}
__device__ __forceinline__ void ldsm_x4_t(uint32_t& r0, uint32_t& r1, uint32_t& r2, uint32_t& r3,
                                          const void* p) {
    uint32_t a = (uint32_t)__cvta_generic_to_shared(p);
    asm volatile("ldmatrix.sync.aligned.m8n8.x4.trans.shared.b16 {%0,%1,%2,%3}, [%4];"
                 : "=r"(r0), "=r"(r1), "=r"(r2), "=r"(r3) : "r"(a));
}

// ---------------- weight split kernel (fp32 -> bf16 hi/lo) -----------------
__global__ __launch_bounds__(256) void split_kernel(
    const float* __restrict__ in, bf16* __restrict__ hi, bf16* __restrict__ lo)
{
    int i = blockIdx.x * blockDim.x + threadIdx.x;
    float4 v = ((const float4*)in)[i];
    bf16 h0,h1,h2,h3,l0,l1,l2,l3;
    split2(v.x,h0,l0); split2(v.y,h1,l1); split2(v.z,h2,l2); split2(v.w,h3,l3);
    bf162 ha; ha.x=h0; ha.y=h1;  bf162 hb; hb.x=h2; hb.y=h3;
    bf162 la; la.x=l0; la.y=l1;  bf162 lb; lb.x=l2; lb.y=l3;
    ((bf162*)hi)[2*i]   = ha; ((bf162*)hi)[2*i+1] = hb;
    ((bf162*)lo)[2*i]   = la; ((bf162*)lo)[2*i+1] = lb;
}

// ---------------- LayerNorm -> split bf16 hi/lo ----------------------------
__global__ __launch_bounds__(256) void layernorm_split_kernel(
    const float* __restrict__ x, const float* __restrict__ g,
    const float* __restrict__ b, bf16* __restrict__ hi, bf16* __restrict__ lo)
{
    int row = blockIdx.x;
    const float4* xr = (const float4*)(x + (size_t)row * DMODEL);
    float4 v = xr[threadIdx.x];
    float s  = v.x + v.y + v.z + v.w;
    float sq = v.x*v.x + v.y*v.y + v.z*v.z + v.w*v.w;
    #pragma unroll
    for (int o = 16; o; o >>= 1) {
        s  += __shfl_xor_sync(0xffffffffu, s,  o);
        sq += __shfl_xor_sync(0xffffffffu, sq, o);
    }
    __shared__ float ss[8], ssq[8];
    int w = threadIdx.x >> 5, lane = threadIdx.x & 31;
    if (lane == 0) { ss[w] = s; ssq[w] = sq; }
    __syncthreads();
    float st = 0.f, sqt = 0.f;
    #pragma unroll
    for (int k = 0; k < 8; k++) { st += ss[k]; sqt += ssq[k]; }
    float mean = st * (1.0f / DMODEL);
    float var  = sqt * (1.0f / DMODEL) - mean * mean;
    float inv  = rsqrtf(var + LN_EPS);
    float4 gg = ((const float4*)g)[threadIdx.x];
    float4 bb = ((const float4*)b)[threadIdx.x];
    float o0 = (v.x - mean) * inv * gg.x + bb.x;
    float o1 = (v.y - mean) * inv * gg.y + bb.y;
    float o2 = (v.z - mean) * inv * gg.z + bb.z;
    float o3 = (v.w - mean) * inv * gg.w + bb.w;
    bf16 h0,h1,h2,h3,l0,l1,l2,l3;
    split2(o0,h0,l0); split2(o1,h1,l1); split2(o2,h2,l2); split2(o3,h3,l3);
    bf162 ha; ha.x=h0; ha.y=h1;  bf162 hb; hb.x=h2; hb.y=h3;
    bf162 la; la.x=l0; la.y=l1;  bf162 lb; lb.x=l2; lb.y=l3;
    bf162* hp = (bf162*)(hi + (size_t)row * DMODEL);
    bf162* lp = (bf162*)(lo + (size_t)row * DMODEL);
    hp[2*threadIdx.x] = ha; hp[2*threadIdx.x+1] = hb;
    lp[2*threadIdx.x] = la; lp[2*threadIdx.x+1] = lb;
}

// ---------------- bf16x3 tensor-core GEMM (ldmatrix mainloop) --------------
// MODE 1: gelu -> split bf16; MODE 2: fp32 bias+resid; MODE 3: bf16 out
// PASSES 3: Ah*Bh + Al*Bh + Ah*Bl;  PASSES 2: Ah*Bh + Al*Bh (Bl never loaded)
#define BM 128
#define BN 128
#define BK 32
#define SSTRIDE 40
#define TILE_B  (BM * SSTRIDE * 2)
#define STAGE_B (4 * TILE_B)

template<int MODE, int PASSES>
__global__ __launch_bounds__(256, 2) void gemm_bf16x3(
    const bf16* __restrict__ Ah, const bf16* __restrict__ Al,
    const bf16* __restrict__ Bh, const bf16* __restrict__ Bl,
    const float* __restrict__ bias, const float* __restrict__ R,
    float* __restrict__ C, bf16* __restrict__ Chi, bf16* __restrict__ Clo,
    int M, int N, int K)
{
    extern __shared__ char smem[];
    const int tid  = threadIdx.x;
    const int bm = blockIdx.y * BM, bn = blockIdx.x * BN;
    const int warp = tid >> 5, lane = tid & 31;
    const int wm = warp >> 2, wn = warp & 3;
    const int gg = lane >> 2, qt = lane & 3;
    const int g8 = lane >> 3, lr = lane & 7;

    const bf16* gmat0 = Ah + (size_t)bm * K;
    const bf16* gmat1 = Al + (size_t)bm * K;
    const bf16* gmat2 = Bh + (size_t)bn * K;
    const bf16* gmat3 = (PASSES == 3) ? (Bl + (size_t)bn * K) : nullptr;

    float acc[4][4][4];
    #pragma unroll
    for (int i = 0; i < 4; i++)
        #pragma unroll
        for (int j = 0; j < 4; j++)
            #pragma unroll
            for (int q = 0; q < 4; q++) acc[i][j][q] = 0.f;

    const int NK = K / BK;

    auto issue = [&](int k0, int st) {
        char* sb = smem + st * STAGE_B;
        #pragma unroll
        for (int c = 0; c < 2; c++) {
            int chunk = tid + c * 256;
            int row = chunk >> 2, col = chunk & 3;
            size_t goff = (size_t)row * K + k0 + col * 8;
            char*  sdst = sb + row * (SSTRIDE * 2) + col * 16;
            cp16(sdst + 0 * TILE_B, gmat0 + goff);
            cp16(sdst + 1 * TILE_B, gmat1 + goff);
            cp16(sdst + 2 * TILE_B, gmat2 + goff);
            if (PASSES == 3) cp16(sdst + 3 * TILE_B, gmat3 + goff);
        }
    };

    issue(0, 0); cp_commit();

    const int a_row = (g8 & 1) * 8 + lr;
    const int a_col = (g8 >> 1) * 8;
    const int b_row = (g8 >> 1) * 8 + lr;
    const int b_col = (g8 & 1) * 8;

    for (int ks = 0; ks < NK; ks++) {
        const int cur = ks & 1;
        if (ks + 1 < NK) { issue((ks + 1) * BK, cur ^ 1); cp_commit(); cp_wait<1>(); }
        else             { cp_wait<0>(); }
        __syncthreads();

        const bf16* sAh = (const bf16*)(smem + cur * STAGE_B);
        const bf16* sAl = sAh + BM * SSTRIDE;
        const bf16* sBh = sAl + BM * SSTRIDE;
        const bf16* sBl = sBh + BM * SSTRIDE;

        #pragma unroll
        for (int kk = 0; kk < BK; kk += 16) {
            uint32_t afr[4][4], bfr[4][2];
            #pragma unroll
            for (int mt = 0; mt < 4; mt++) {
                const bf16* p = sAh + (wm*64 + mt*16 + a_row) * SSTRIDE + kk + a_col;
                ldsm_x4(afr[mt][0], afr[mt][1], afr[mt][2], afr[mt][3], p);
            }
            #pragma unroll
            for (int np = 0; np < 2; np++) {
                const bf16* p = sBh + (wn*32 + np*16 + b_row) * SSTRIDE + kk + b_col;
                ldsm_x4(bfr[2*np][0], bfr[2*np][1], bfr[2*np+1][0], bfr[2*np+1][1], p);
            }
            // Ah * Bh
            #pragma unroll
            for (int mt = 0; mt < 4; mt++)
                #pragma unroll
                for (int nt = 0; nt < 4; nt++)
                    mma16816(acc[mt][nt], afr[mt], bfr[nt]);
            // Al * Bh
            {
                uint32_t afl[4][4];
                #pragma unroll
                for (int mt = 0; mt < 4; mt++) {
                    const bf16* p = sAl + (wm*64 + mt*16 + a_row) * SSTRIDE + kk + a_col;
                    ldsm_x4(afl[mt][0], afl[mt][1], afl[mt][2], afl[mt][3], p);
                }
                #pragma unroll
                for (int mt = 0; mt < 4; mt++)
                    #pragma unroll
                    for (int nt = 0; nt < 4; nt++)
                        mma16816(acc[mt][nt], afl[mt], bfr[nt]);
            }
            // Ah * Bl (pass 3 only)
            if (PASSES == 3) {
                #pragma unroll
                for (int np = 0; np < 2; np++) {
                    const bf16* p = sBl + (wn*32 + np*16 + b_row) * SSTRIDE + kk + b_col;
                    ldsm_x4(bfr[2*np][0], bfr[2*np][1], bfr[2*np+1][0], bfr[2*np+1][1], p);
                }
                #pragma unroll
                for (int mt = 0; mt < 4; mt++)
                    #pragma unroll
                    for (int nt = 0; nt < 4; nt++)
                        mma16816(acc[mt][nt], afr[mt], bfr[nt]);
            }
        }
        __syncthreads();
    }

    #pragma unroll
    for (int mt = 0; mt < 4; mt++) {
        #pragma unroll
        for (int nt = 0; nt < 4; nt++) {
            int r  = bm + wm * 64 + mt * 16 + gg;
            int c0 = bn + wn * 32 + nt * 8 + 2 * qt;
            float2 bv = *(const float2*)(bias + c0);
            float v00 = acc[mt][nt][0] + bv.x;
            float v01 = acc[mt][nt][1] + bv.y;
            float v10 = acc[mt][nt][2] + bv.x;
            float v11 = acc[mt][nt][3] + bv.y;
            if (MODE == 2) {
                float2 r0 = *(const float2*)(R + (size_t)r * N + c0);
                float2 r1 = *(const float2*)(R + (size_t)(r + 8) * N + c0);
                v00 += r0.x; v01 += r0.y; v10 += r1.x; v11 += r1.y;
            }
            if (MODE == 1) {
                v00 = gelu_exact(v00); v01 = gelu_exact(v01);
                v10 = gelu_exact(v10); v11 = gelu_exact(v11);
                bf16 h0,h1,h2,h3,l0,l1,l2,l3;
                split2(v00,h0,l0); split2(v01,h1,l1);
                split2(v10,h2,l2); split2(v11,h3,l3);
                bf162 pa; pa.x=h0; pa.y=h1;  bf162 pb; pb.x=h2; pb.y=h3;
                bf162 qa; qa.x=l0; qa.y=l1;  bf162 qb; qb.x=l2; qb.y=l3;
                *(bf162*)(Chi + (size_t)r * N + c0)       = pa;
                *(bf162*)(Chi + (size_t)(r + 8) * N + c0) = pb;
                *(bf162*)(Clo + (size_t)r * N + c0)       = qa;
                *(bf162*)(Clo + (size_t)(r + 8) * N + c0) = qb;
            } else if (MODE == 3) {
                uint32_t pa = pk2(v00, v01);
                uint32_t pb = pk2(v10, v11);
                *(uint32_t*)(Chi + (size_t)r * N + c0)       = pa;
                *(uint32_t*)(Chi + (size_t)(r + 8) * N + c0) = pb;
            } else {
                *(float2*)(C + (size_t)r * N + c0)       = make_float2(v00, v01);
                *(float2*)(C + (size_t)(r + 8) * N + c0) = make_float2(v10, v11);
            }
        }
    }
}

// ---------------- tensor-core causal flash attention -----------------------
#define KSTR 72   // bf16 elems per smem row (64 data + 8 pad -> 144B stride)

__global__ __launch_bounds__(256) void attn_mma_kernel(
    const bf16* __restrict__ qkvb, bf16* __restrict__ o_hi, bf16* __restrict__ o_lo)
{
    extern __shared__ char asmem[];
    bf16* Qs = (bf16*)asmem;
    bf16* Ks = Qs + 128 * KSTR;
    bf16* Vs = Ks + 2 * 64 * KSTR;

    const int tid = threadIdx.x;
    const int warp = tid >> 5, lane = tid & 31;
    const int gg = lane >> 2, qt = lane & 3;
    const int g8 = lane >> 3, lr = lane & 7;
    const int qt_blk = blockIdx.x, bh = blockIdx.y;
    const int b = bh >> 4, h = bh & 15;
    const int q0 = qt_blk * 128;
    const size_t ROW = 3 * DMODEL;
    const bf16* qg = qkvb + (size_t)(b * SEQ) * ROW + h * HDIM;
    const bf16* kg = qg + DMODEL;
    const bf16* vg = qg + 2 * DMODEL;

    #pragma unroll
    for (int u = 0; u < 4; u++) {
        int idx = tid + u * 256;
        int r = idx >> 3, c = (idx & 7) * 8;
        *(uint4*)&Qs[r * KSTR + c] = *(const uint4*)(qg + (size_t)(q0 + r) * ROW + c);
    }
    __syncthreads();

    uint32_t qf[4][4];
    {
        const bf162 sc = __floats2bfloat162_rn(0.125f, 0.125f);
        #pragma unroll
        for (int kt = 0; kt < 4; kt++) {
            const bf16* p = &Qs[(warp * 16 + (g8 & 1) * 8 + lr) * KSTR + kt * 16 + (g8 >> 1) * 8];
            ldsm_x4(qf[kt][0], qf[kt][1], qf[kt][2], qf[kt][3], p);
            #pragma unroll
            for (int i = 0; i < 4; i++) {
                bf162 v = *(bf162*)&qf[kt][i];
                v = __hmul2(v, sc);
                qf[kt][i] = *(uint32_t*)&v;
            }
        }
    }

    float oacc[8][4];
    #pragma unroll
    for (int nt = 0; nt < 8; nt++)
        #pragma unroll
        for (int i = 0; i < 4; i++) oacc[nt][i] = 0.f;
    float m0 = -1e30f, m1 = -1e30f, l0 = 0.f, l1 = 0.f;

    const int ntiles = qt_blk * 2 + 2;
    const int wbase = q0 + warp * 16;
    const int wmax  = wbase + 15;

    auto issue = [&](int t, int st) {
        #pragma unroll
        for (int u = 0; u < 2; u++) {
            int idx = tid + u * 256;
            int r = idx >> 3, c = (idx & 7) * 8;
            size_t goff = (size_t)(t * 64 + r) * ROW + c;
            cp16(&Ks[st * 64 * KSTR + r * KSTR + c], kg + goff);
            cp16(&Vs[st * 64 * KSTR + r * KSTR + c], vg + goff);
        }
    };

    issue(0, 0); cp_commit();

    for (int t = 0; t < ntiles; t++) {
        const int cur = t & 1;
        if (t + 1 < ntiles) { issue(t + 1, cur ^ 1); cp_commit(); cp_wait<1>(); }
        else                { cp_wait<0>(); }
        __syncthreads();

        const int j0 = t * 64;
        if (j0 <= wmax) {
            const bf16* Kt = &Ks[cur * 64 * KSTR];
            const bf16* Vt = &Vs[cur * 64 * KSTR];

            float sacc[8][4];
            #pragma unroll
            for (int nt = 0; nt < 8; nt++)
                #pragma unroll
                for (int i = 0; i < 4; i++) sacc[nt][i] = 0.f;

            #pragma unroll
            for (int kt = 0; kt < 4; kt++) {
                uint32_t bfr[8][2];
                #pragma unroll
                for (int np = 0; np < 4; np++) {
                    const bf16* p = &Kt[(np * 16 + (g8 >> 1) * 8 + lr) * KSTR + kt * 16 + (g8 & 1) * 8];
                    ldsm_x4(bfr[2*np][0], bfr[2*np][1], bfr[2*np+1][0], bfr[2*np+1][1], p);
                }
                #pragma unroll
                for (int nt = 0; nt < 8; nt++)
                    mma16816(sacc[nt], qf[kt], bfr[nt]);
            }

            const int r0 = wbase + gg, r1 = r0 + 8;
            if (j0 + 63 > wbase) {
                #pragma unroll
                for (int nt = 0; nt < 8; nt++) {
                    int c0 = j0 + nt * 8 + 2 * qt, c1 = c0 + 1;
                    if (c0 > r0) sacc[nt][0] = -1e30f;
                    if (c1 > r0) sacc[nt][1] = -1e30f;
                    if (c0 > r1) sacc[nt][2] = -1e30f;
                    if (c1 > r1) sacc[nt][3] = -1e30f;
                }
            }

            float mx0 = -1e30f, mx1 = -1e30f;
            #pragma unroll
            for (int nt = 0; nt < 8; nt++) {
                mx0 = fmaxf(mx0, fmaxf(sacc[nt][0], sacc[nt][1]));
                mx1 = fmaxf(mx1, fmaxf(sacc[nt][2], sacc[nt][3]));
            }
            mx0 = fmaxf(mx0, __shfl_xor_sync(0xffffffffu, mx0, 1));
            mx0 = fmaxf(mx0, __shfl_xor_sync(0xffffffffu, mx0, 2));
            mx1 = fmaxf(mx1, __shfl_xor_sync(0xffffffffu, mx1, 1));
            mx1 = fmaxf(mx1, __shfl_xor_sync(0xffffffffu, mx1, 2));
            float mn0 = fmaxf(m0, mx0), mn1 = fmaxf(m1, mx1);
            float cr0 = __expf(m0 - mn0), cr1 = __expf(m1 - mn1);
            m0 = mn0; m1 = mn1;

            float ps0 = 0.f, ps1 = 0.f;
            uint32_t pa[4][4];
            #pragma unroll
            for (int np = 0; np < 4; np++) {
                float e00 = __expf(sacc[2*np  ][0] - mn0);
                float e01 = __expf(sacc[2*np  ][1] - mn0);
                float e02 = __expf(sacc[2*np  ][2] - mn1);
                float e03 = __expf(sacc[2*np  ][3] - mn1);
                float e10 = __expf(sacc[2*np+1][0] - mn0);
                float e11 = __expf(sacc[2*np+1][1] - mn0);
                float e12 = __expf(sacc[2*np+1][2] - mn1);
                float e13 = __expf(sacc[2*np+1][3] - mn1);
                ps0 += e00 + e01 + e10 + e11;
                ps1 += e02 + e03 + e12 + e13;
                pa[np][0] = pk2(e00, e01);
                pa[np][1] = pk2(e02, e03);
                pa[np][2] = pk2(e10, e11);
                pa[np][3] = pk2(e12, e13);
            }
            ps0 += __shfl_xor_sync(0xffffffffu, ps0, 1);
            ps0 += __shfl_xor_sync(0xffffffffu, ps0, 2);
            ps1 += __shfl_xor_sync(0xffffffffu, ps1, 1);
            ps1 += __shfl_xor_sync(0xffffffffu, ps1, 2);
            l0 = l0 * cr0 + ps0;
            l1 = l1 * cr1 + ps1;
            #pragma unroll
            for (int nt = 0; nt < 8; nt++) {
                oacc[nt][0] *= cr0; oacc[nt][1] *= cr0;
                oacc[nt][2] *= cr1; oacc[nt][3] *= cr1;
            }

            #pragma unroll
            for (int kt = 0; kt < 4; kt++) {
                uint32_t vfr[8][2];
                #pragma unroll
                for (int np = 0; np < 4; np++) {
                    const bf16* p = &Vt[(kt * 16 + (g8 & 1) * 8 + lr) * KSTR + np * 16 + (g8 >> 1) * 8];
                    ldsm_x4_t(vfr[2*np][0], vfr[2*np][1], vfr[2*np+1][0], vfr[2*np+1][1], p);
                }
                #pragma unroll
                for (int nt = 0; nt < 8; nt++)
                    mma16816(oacc[nt], pa[kt], vfr[nt]);
            }
        }
        __syncthreads();
    }

    float inv0 = 1.f / l0, inv1 = 1.f / l1;
    int grow0 = b * SEQ + wbase + gg;
    int grow1 = grow0 + 8;
    #pragma unroll
    for (int nt = 0; nt < 8; nt++) {
        int col = h * HDIM + nt * 8 + 2 * qt;
        float v00 = oacc[nt][0] * inv0, v01 = oacc[nt][1] * inv0;
        float v10 = oacc[nt][2] * inv1, v11 = oacc[nt][3] * inv1;
        bf16 h0,h1,h2,h3,l0b,l1b,l2b,l3b;
        split2(v00,h0,l0b); split2(v01,h1,l1b);
        split2(v10,h2,l2b); split2(v11,h3,l3b);
        bf162 pa; pa.x=h0; pa.y=h1;  bf162 pb; pb.x=h2; pb.y=h3;
        bf162 qa; qa.x=l0b; qa.y=l1b; bf162 qb; qb.x=l2b; qb.y=l3b;
        *(bf162*)(o_hi + (size_t)grow0 * DMODEL + col) = pa;
        *(bf162*)(o_hi + (size_t)grow1 * DMODEL + col) = pb;
        *(bf162*)(o_lo + (size_t)grow0 * DMODEL + col) = qa;
        *(bf162*)(o_lo + (size_t)grow1 * DMODEL + col) = qb;
    }
}

// ---------------- launch ----------------
extern "C" void kernel_launch(void* const* d_in, const int* in_sizes, int n_in,
                              void* d_out, int out_size)
{
    const float* x     = (const float*)d_in[0];
    const float* ln1_g = (const float*)d_in[1];
    const float* ln1_b = (const float*)d_in[2];
    const float* qkv_w = (const float*)d_in[3];
    const float* qkv_b = (const float*)d_in[4];
    const float* out_w = (const float*)d_in[5];
    const float* out_b = (const float*)d_in[6];
    const float* ln2_g = (const float*)d_in[7];
    const float* ln2_b = (const float*)d_in[8];
    const float* fc1_w = (const float*)d_in[9];
    const float* fc1_b = (const float*)d_in[10];
    const float* fc2_w = (const float*)d_in[11];
    const float* fc2_b = (const float*)d_in[12];
    float* out = (float*)d_out;

    static bf16 *p_qkvb = nullptr;
    static bf16 *p_h_hi, *p_h_lo, *p_o_hi, *p_o_lo, *p_h2_hi, *p_h2_lo;
    static bf16 *p_wqkv_hi, *p_wqkv_lo, *p_wout_hi, *p_wout_lo;
    static bf16 *p_wfc1_hi, *p_wfc1_lo, *p_wfc2_hi, *p_wfc2_lo;
    if (!p_qkvb) {
        cudaGetSymbolAddress((void**)&p_qkvb,   g_qkvb);
        cudaGetSymbolAddress((void**)&p_h_hi,   g_h_hi);
        cudaGetSymbolAddress((void**)&p_h_lo,   g_h_lo);
        cudaGetSymbolAddress((void**)&p_o_hi,   g_o_hi);
        cudaGetSymbolAddress((void**)&p_o_lo,   g_o_lo);
        cudaGetSymbolAddress((void**)&p_h2_hi,  g_h2_hi);
        cudaGetSymbolAddress((void**)&p_h2_lo,  g_h2_lo);
        cudaGetSymbolAddress((void**)&p_wqkv_hi, g_wqkv_hi);
        cudaGetSymbolAddress((void**)&p_wqkv_lo, g_wqkv_lo);
        cudaGetSymbolAddress((void**)&p_wout_hi, g_wout_hi);
        cudaGetSymbolAddress((void**)&p_wout_lo, g_wout_lo);
        cudaGetSymbolAddress((void**)&p_wfc1_hi, g_wfc1_hi);
        cudaGetSymbolAddress((void**)&p_wfc1_lo, g_wfc1_lo);
        cudaGetSymbolAddress((void**)&p_wfc2_hi, g_wfc2_hi);
        cudaGetSymbolAddress((void**)&p_wfc2_lo, g_wfc2_lo);
    }

    const int SMEM_GEMM = 2 * STAGE_B;                    // 81920
    const int SMEM_ATTN = (128 + 2*64 + 2*64) * KSTR * 2; // 55296
    cudaFuncSetAttribute((const void*)gemm_bf16x3<1,3>, cudaFuncAttributeMaxDynamicSharedMemorySize, SMEM_GEMM);
    cudaFuncSetAttribute((const void*)gemm_bf16x3<2,3>, cudaFuncAttributeMaxDynamicSharedMemorySize, SMEM_GEMM);
    cudaFuncSetAttribute((const void*)gemm_bf16x3<2,2>, cudaFuncAttributeMaxDynamicSharedMemorySize, SMEM_GEMM);
    cudaFuncSetAttribute((const void*)gemm_bf16x3<3,2>, cudaFuncAttributeMaxDynamicSharedMemorySize, SMEM_GEMM);
    cudaFuncSetAttribute((const void*)attn_mma_kernel,  cudaFuncAttributeMaxDynamicSharedMemorySize, SMEM_ATTN);

    // weight splits
    split_kernel<<<(3*DMODEL*DMODEL)/4/256, 256>>>(qkv_w, p_wqkv_hi, p_wqkv_lo);
    split_kernel<<<(DMODEL*DMODEL)/4/256,   256>>>(out_w, p_wout_hi, p_wout_lo);
    split_kernel<<<(DFF*DMODEL)/4/256,      256>>>(fc1_w, p_wfc1_hi, p_wfc1_lo);
    split_kernel<<<(DMODEL*DFF)/4/256,      256>>>(fc2_w, p_wfc2_hi, p_wfc2_lo);

    // 1. h = LN1(x) -> split
    layernorm_split_kernel<<<MROWS, 256>>>(x, ln1_g, ln1_b, p_h_hi, p_h_lo);
    // 2. qkv = h @ qkv_w^T + qkv_b (bf16 out; 2-pass — output is bf16-rounded anyway)
    gemm_bf16x3<3,2><<<dim3(3*DMODEL/BN, MROWS/BM), 256, SMEM_GEMM>>>(
        p_h_hi, p_h_lo, p_wqkv_hi, p_wqkv_lo, qkv_b, nullptr,
        nullptr, p_qkvb, nullptr, MROWS, 3*DMODEL, DMODEL);
    // 3. attention -> o split
    attn_mma_kernel<<<dim3(SEQ/128, BATCH*NHEADS), 256, SMEM_ATTN>>>(p_qkvb, p_o_hi, p_o_lo);
    // 4. out = x + o @ out_w^T + out_b  (3-pass)
    gemm_bf16x3<2,3><<<dim3(DMODEL/BN, MROWS/BM), 256, SMEM_GEMM>>>(
        p_o_hi, p_o_lo, p_wout_hi, p_wout_lo, out_b, x,
        out, nullptr, nullptr, MROWS, DMODEL, DMODEL);
    // 5. h = LN2(out) -> split
    layernorm_split_kernel<<<MROWS, 256>>>(out, ln2_g, ln2_b, p_h_hi, p_h_lo);
    // 6. h2 = gelu(h @ fc1_w^T + fc1_b) -> split  (3-pass)
    gemm_bf16x3<1,3><<<dim3(DFF/BN, MROWS/BM), 256, SMEM_GEMM>>>(
        p_h_hi, p_h_lo, p_wfc1_hi, p_wfc1_lo, fc1_b, nullptr,
        nullptr, p_h2_hi, p_h2_lo, MROWS, DFF, DMODEL);
    // 7. out = out + h2 @ fc2_w^T + fc2_b  (2-pass — weight-lo dropped, ~6e-4 budget)
    gemm_bf16x3<2,2><<<dim3(DMODEL/BN, MROWS/BM), 256, SMEM_GEMM>>>(
        p_h2_hi, p_h2_lo, p_wfc2_hi, p_wfc2_lo, fc2_b, out,
        out, nullptr, nullptr, MROWS, DMODEL, DFF);
}